// round 5
// baseline (speedup 1.0000x reference)
#include <cuda_runtime.h>
#include <cstdint>
#include <cstddef>

// Problem constants
#define T_TOK   4096
#define HDIM    1024
#define IDIM    2048
#define NEXP    8
#define TOPK    2
#define NROWS_ROUTED (T_TOK * TOPK)         // 8192
#define NROWS_TOTAL  (NROWS_ROUTED + T_TOK) // 12288
#define ROUTER_BLOCKS (T_TOK / 8)           // 512

#define OUT_AUX    (T_TOK * HDIM)
#define OUT_Z      (OUT_AUX + 1)
#define OUT_LOGITS (OUT_AUX + 2)

// ---------------- scratch ----------------------------------------------------
__device__ int   g_count[NEXP];
__device__ int   g_list[NEXP * T_TOK];
__device__ float g_wgt [NEXP * T_TOK];
__device__ int   g_rowbase[NEXP + 1];
__device__ int   g_ctok[NROWS_TOTAL];
__device__ float g_cwgt[NROWS_TOTAL];
__device__ float g_pp[ROUTER_BLOCKS * NEXP];
__device__ float g_pl[ROUTER_BLOCKS];

// packed (tf32-rounded, k-pair {k,k+4} layout) operands
__device__ float g_Xp [(size_t)T_TOK * HDIM];            // 16.8 MB
__device__ float g_Gp [(size_t)NROWS_TOTAL * IDIM];      // 100 MB (h, packed)
__device__ float g_gWp[(size_t)NEXP * HDIM * IDIM];      // 67 MB
__device__ float g_uWp[(size_t)NEXP * HDIM * IDIM];      // 67 MB
__device__ float g_dWp[(size_t)NEXP * IDIM * HDIM];      // 67 MB
__device__ float g_sgWp[(size_t)HDIM * IDIM];
__device__ float g_suWp[(size_t)HDIM * IDIM];
__device__ float g_sdWp[(size_t)IDIM * HDIM];

// ---------------- helpers -----------------------------------------------------
__device__ __forceinline__ uint32_t f2tf32(float f) {
    uint32_t r;
    asm("cvt.rna.tf32.f32 %0, %1;" : "=r"(r) : "f"(f));
    return r;
}
__device__ __forceinline__ float f2tf32f(float f) {
    return __uint_as_float(f2tf32(f));
}
__device__ __forceinline__ void cp_async16(uint32_t s, const void* g) {
    asm volatile("cp.async.cg.shared.global [%0], [%1], 16;\n" :: "r"(s), "l"(g));
}
__device__ __forceinline__ void cp_commit() {
    asm volatile("cp.async.commit_group;\n");
}
template <int N>
__device__ __forceinline__ void cp_wait() {
    asm volatile("cp.async.wait_group %0;\n" :: "n"(N));
}
__device__ __forceinline__ void mma_tf32(float* d, const uint32_t* a, const uint32_t* b) {
    asm volatile(
        "mma.sync.aligned.m16n8k8.row.col.f32.tf32.tf32.f32 "
        "{%0,%1,%2,%3},{%4,%5,%6,%7},{%8,%9},{%0,%1,%2,%3};"
        : "+f"(d[0]), "+f"(d[1]), "+f"(d[2]), "+f"(d[3])
        : "r"(a[0]), "r"(a[1]), "r"(a[2]), "r"(a[3]), "r"(b[0]), "r"(b[1]));
}

// ---------------- kernel: zero counters --------------------------------------
__global__ void zero_counts_kernel() {
    if (threadIdx.x < NEXP) g_count[threadIdx.x] = 0;
}

// ---------------- router ------------------------------------------------------
__global__ void __launch_bounds__(256) router_kernel(
    const float* __restrict__ x, const float* __restrict__ rw,
    float* __restrict__ out)
{
    const int warp = threadIdx.x >> 5, lane = threadIdx.x & 31;
    const int t = blockIdx.x * 8 + warp;

    float acc[NEXP];
#pragma unroll
    for (int e = 0; e < NEXP; e++) acc[e] = 0.f;

    const float* xr = x + (size_t)t * HDIM;
    for (int h = lane; h < HDIM; h += 32) {
        float xv = xr[h];
        const float* r = rw + (size_t)h * NEXP;
#pragma unroll
        for (int e = 0; e < NEXP; e++) acc[e] += xv * r[e];
    }
#pragma unroll
    for (int off = 16; off > 0; off >>= 1)
#pragma unroll
        for (int e = 0; e < NEXP; e++)
            acc[e] += __shfl_xor_sync(0xFFFFFFFFu, acc[e], off);

    __shared__ float s_prob[8][NEXP];
    __shared__ float s_lse2[8];

    if (lane == 0) {
        float mx = acc[0];
#pragma unroll
        for (int e = 1; e < NEXP; e++) mx = fmaxf(mx, acc[e]);
        float p[NEXP], sum = 0.f;
#pragma unroll
        for (int e = 0; e < NEXP; e++) { p[e] = expf(acc[e] - mx); sum += p[e]; }
        float lse = logf(sum) + mx;
        s_lse2[warp] = lse * lse;
        float inv = 1.f / sum;
#pragma unroll
        for (int e = 0; e < NEXP; e++) {
            p[e] *= inv;
            s_prob[warp][e] = p[e];
            out[OUT_LOGITS + (size_t)t * NEXP + e] = acc[e];
        }
        int i1 = 0;
#pragma unroll
        for (int e = 1; e < NEXP; e++) if (p[e] > p[i1]) i1 = e;
        int i2 = (i1 == 0) ? 1 : 0;
#pragma unroll
        for (int e = 0; e < NEXP; e++) if (e != i2 && e != i1 && p[e] > p[i2]) i2 = e;
        float s2 = p[i1] + p[i2];
        float w1 = p[i1] / s2, w2 = p[i2] / s2;
        int pos1 = atomicAdd(&g_count[i1], 1);
        g_list[i1 * T_TOK + pos1] = t; g_wgt[i1 * T_TOK + pos1] = w1;
        int pos2 = atomicAdd(&g_count[i2], 1);
        g_list[i2 * T_TOK + pos2] = t; g_wgt[i2 * T_TOK + pos2] = w2;
    }
    __syncthreads();
    if (threadIdx.x == 0) {
        float ps[NEXP]; float l2 = 0.f;
#pragma unroll
        for (int e = 0; e < NEXP; e++) ps[e] = 0.f;
        for (int w = 0; w < 8; w++) {
            l2 += s_lse2[w];
#pragma unroll
            for (int e = 0; e < NEXP; e++) ps[e] += s_prob[w][e];
        }
#pragma unroll
        for (int e = 0; e < NEXP; e++) g_pp[blockIdx.x * NEXP + e] = ps[e];
        g_pl[blockIdx.x] = l2;
    }
}

// ---------------- finalize ----------------------------------------------------
__global__ void finalize_kernel(float* __restrict__ out) {
    const int warp = threadIdx.x >> 5, lane = threadIdx.x & 31;
    __shared__ float red[NEXP + 1];
    if (warp < NEXP) {
        float s = 0.f;
        for (int j = 0; j < ROUTER_BLOCKS / 32; j++)
            s += g_pp[(size_t)(lane + 32 * j) * NEXP + warp];
#pragma unroll
        for (int off = 16; off > 0; off >>= 1) s += __shfl_xor_sync(0xFFFFFFFFu, s, off);
        if (lane == 0) red[warp] = s;
    } else if (warp == NEXP) {
        float s = 0.f;
        for (int j = 0; j < ROUTER_BLOCKS / 32; j++)
            s += g_pl[lane + 32 * j];
#pragma unroll
        for (int off = 16; off > 0; off >>= 1) s += __shfl_xor_sync(0xFFFFFFFFu, s, off);
        if (lane == 0) red[NEXP] = s;
    }
    __syncthreads();
    if (threadIdx.x == 0) {
        float aux = 0.f;
        int rb = 0;
        for (int e = 0; e < NEXP; e++) {
            aux += ((float)g_count[e] / (float)(T_TOK * TOPK)) * (red[e] / (float)T_TOK);
            g_rowbase[e] = rb;
            rb += g_count[e];
        }
        g_rowbase[NEXP] = NROWS_ROUTED;
        out[OUT_AUX] = (float)NEXP * aux;
        out[OUT_Z]   = red[NEXP] / (float)T_TOK;
    }
}

// ---------------- compact -----------------------------------------------------
__global__ void compact_kernel() {
    int idx = blockIdx.x * blockDim.x + threadIdx.x;
    int e = idx / T_TOK, pos = idx % T_TOK;
    if (e < NEXP) {
        if (pos < g_count[e]) {
            int cr = g_rowbase[e] + pos;
            g_ctok[cr] = g_list[e * T_TOK + pos];
            g_cwgt[cr] = g_wgt[e * T_TOK + pos];
        }
    } else {
        g_ctok[NROWS_ROUTED + pos] = pos;
        g_cwgt[NROWS_ROUTED + pos] = 1.f;
    }
}

// ---------------- pack X: tf32 + pair-pack per 16-k panel ---------------------
// pair layout within panel: float idx = p*2 + elem, p=(kk&3)|((kk&8)>>1),
// elem=(kk&4)>>2  => pairs {k, k+4}.
__global__ void pack_x_kernel(const float* __restrict__ x) {
    int idx = blockIdx.x * blockDim.x + threadIdx.x;  // T_TOK*64
    const float* s = x + (size_t)idx * 16;
    float4 v0 = *(const float4*)(s + 0);
    float4 v1 = *(const float4*)(s + 4);
    float4 v2 = *(const float4*)(s + 8);
    float4 v3 = *(const float4*)(s + 12);
    float* d = g_Xp + (size_t)idx * 16;
    *(float4*)(d + 0)  = make_float4(f2tf32f(v0.x), f2tf32f(v1.x), f2tf32f(v0.y), f2tf32f(v1.y));
    *(float4*)(d + 4)  = make_float4(f2tf32f(v0.z), f2tf32f(v1.z), f2tf32f(v0.w), f2tf32f(v1.w));
    *(float4*)(d + 8)  = make_float4(f2tf32f(v2.x), f2tf32f(v3.x), f2tf32f(v2.y), f2tf32f(v3.y));
    *(float4*)(d + 12) = make_float4(f2tf32f(v2.z), f2tf32f(v3.z), f2tf32f(v2.w), f2tf32f(v3.w));
}

// ---------------- pack W: tf32 + pair-pack, [kt][p][n] float2 -----------------
__global__ void pack_w_kernel(const float* __restrict__ src, float* __restrict__ dst,
                              int N, int NG /* N/4 */) {
    int idx = blockIdx.x * blockDim.x + threadIdx.x;   // KT*8*NG
    int n4 = idx % NG;
    int rest = idx / NG;
    int p = rest & 7, kt = rest >> 3;
    int kk0 = (p & 3) + ((p & 4) << 1);
    size_t k0 = (size_t)(kt * 16 + kk0);
    float4 a = *(const float4*)(src + k0 * N + n4 * 4);
    float4 b = *(const float4*)(src + (k0 + 4) * N + n4 * 4);
    float* d = dst + ((size_t)(kt * 8 + p) * N + n4 * 4) * 2;
    *(float4*)(d + 0) = make_float4(f2tf32f(a.x), f2tf32f(b.x), f2tf32f(a.y), f2tf32f(b.y));
    *(float4*)(d + 4) = make_float4(f2tf32f(a.z), f2tf32f(b.z), f2tf32f(a.w), f2tf32f(b.w));
}

// ============================================================================
// Fused gate+up+act GEMM. 256 thr (8 warps, 2m x 4n), block 128x128 (both
// matrices), warp 64x32 each. 4-stage cp.async pipeline, ALL operands packed
// tf32 pairs, fragment loads are LDS.64, zero CVT in mainloop.
// ============================================================================
#define NST   4
#define A_ST2 12     // float2 per A row
#define B_ST2 132    // float2 per B pair-row
#define A_SF2 (128 * A_ST2)   // 1536 float2 per A stage
#define B_SF2 (8 * B_ST2)     // 1056 float2 per B stage

__global__ void __launch_bounds__(256, 1) gemm_gu_fused(
    const float* __restrict__ gWp, const float* __restrict__ uWp,
    const float* __restrict__ sgWp, const float* __restrict__ suWp)
{
    const int e = blockIdx.z;
    const int n_e = (e < NEXP) ? g_count[e] : T_TOK;
    const int m0 = blockIdx.y * 128;
    if (m0 >= n_e) return;
    const int base = g_rowbase[e];
    const float* __restrict__ Bg = (e < NEXP) ? (gWp + (size_t)e * HDIM * IDIM) : sgWp;
    const float* __restrict__ Bu = (e < NEXP) ? (uWp + (size_t)e * HDIM * IDIM) : suWp;
    const int n0 = blockIdx.x * 128;

    const int tid  = threadIdx.x;
    const int warp = tid >> 5, lane = tid & 31;
    const int gi = lane >> 2, tig = lane & 3;
    const int wm = (warp & 1) * 64, wn = (warp >> 1) * 32;

    extern __shared__ float2 sm2[];
    float2* As = sm2;                    // NST * A_SF2
    float2* Bgs = sm2 + NST * A_SF2;     // NST * B_SF2
    float2* Bus = Bgs + NST * B_SF2;
    const uint32_t uAs = (uint32_t)__cvta_generic_to_shared(As);
    const uint32_t uBg = (uint32_t)__cvta_generic_to_shared(Bgs);
    const uint32_t uBu = (uint32_t)__cvta_generic_to_shared(Bus);

    // A producer: 2 threads per row
    const int ar = tid >> 1, ac = tid & 1;
    const float* arow;
    {
        int tok = (m0 + ar < n_e) ? g_ctok[base + m0 + ar] : g_ctok[base];
        arow = g_Xp + (size_t)tok * HDIM + ac * 8;
    }
    // B producer indices (2 chunks per thread per matrix)
    int bp[2], bn[2];
#pragma unroll
    for (int c = 0; c < 2; c++) {
        int idx = c * 256 + tid;
        bp[c] = idx >> 6;
        bn[c] = (idx & 63) * 2;
    }

    float dg[4][4][4], du[4][4][4];
#pragma unroll
    for (int i = 0; i < 4; i++)
#pragma unroll
        for (int j = 0; j < 4; j++)
#pragma unroll
            for (int c = 0; c < 4; c++) { dg[i][j][c] = 0.f; du[i][j][c] = 0.f; }

    auto issue = [&](int kt) {
        const int s = kt & (NST - 1);
        // A: 2 cp16 (row ar, 8 floats at ac*8)
        uint32_t ad = uAs + (uint32_t)((s * A_SF2 + ar * A_ST2 + ac * 4) * 8);
        const float* asrc = arow + kt * 16;
        cp_async16(ad,      asrc);
        cp_async16(ad + 16, asrc + 4);
        // B: 2 chunks per matrix
#pragma unroll
        for (int c = 0; c < 2; c++) {
            size_t goff = ((size_t)(kt * 8 + bp[c]) * IDIM + n0 + bn[c]) * 2;
            uint32_t so = (uint32_t)((s * B_SF2 + bp[c] * B_ST2 + bn[c]) * 8);
            cp_async16(uBg + so, Bg + goff);
            cp_async16(uBu + so, Bu + goff);
        }
        cp_commit();
    };

    const int NK = HDIM / 16;   // 64
    issue(0); issue(1); issue(2);
    for (int kt = 0; kt < NK; kt++) {
        cp_wait<2>();
        __syncthreads();
        if (kt + 3 < NK) issue(kt + 3); else cp_commit();

        const int s = kt & (NST - 1);
        const float2* Ab  = As  + s * A_SF2;
        const float2* Bgb = Bgs + s * B_SF2;
        const float2* Bub = Bus + s * B_SF2;
#pragma unroll
        for (int ks = 0; ks < 2; ks++) {
            const int pc = ks * 4 + tig;
            uint32_t af[4][4];
#pragma unroll
            for (int ms = 0; ms < 4; ms++) {
                const int mB = wm + ms * 16;
                float2 p0 = Ab[(mB + gi) * A_ST2 + pc];
                float2 p1 = Ab[(mB + 8 + gi) * A_ST2 + pc];
                af[ms][0] = __float_as_uint(p0.x);
                af[ms][1] = __float_as_uint(p1.x);
                af[ms][2] = __float_as_uint(p0.y);
                af[ms][3] = __float_as_uint(p1.y);
            }
            uint32_t bf[4][2];
#pragma unroll
            for (int ns = 0; ns < 4; ns++) {
                float2 b = Bgb[pc * B_ST2 + wn + ns * 8 + gi];
                bf[ns][0] = __float_as_uint(b.x);
                bf[ns][1] = __float_as_uint(b.y);
            }
#pragma unroll
            for (int ms = 0; ms < 4; ms++)
#pragma unroll
                for (int ns = 0; ns < 4; ns++)
                    mma_tf32(dg[ms][ns], af[ms], bf[ns]);
#pragma unroll
            for (int ns = 0; ns < 4; ns++) {
                float2 b = Bub[pc * B_ST2 + wn + ns * 8 + gi];
                bf[ns][0] = __float_as_uint(b.x);
                bf[ns][1] = __float_as_uint(b.y);
            }
#pragma unroll
            for (int ms = 0; ms < 4; ms++)
#pragma unroll
                for (int ns = 0; ns < 4; ns++)
                    mma_tf32(du[ms][ns], af[ms], bf[ns]);
        }
    }

    // epilogue: h = w*silu(g)*u, tf32-rounded, written PAIR-PACKED into g_Gp
#pragma unroll
    for (int ms = 0; ms < 4; ms++) {
#pragma unroll
        for (int half = 0; half < 2; half++) {
            const int r = m0 + wm + ms * 16 + half * 8 + gi;
            if (r < n_e) {
                const int row = base + r;
                const float w = g_cwgt[row];
                float* C = g_Gp + (size_t)row * IDIM;
#pragma unroll
                for (int ns = 0; ns < 4; ns++) {
                    const int n = n0 + wn + ns * 8 + 2 * tig;
                    float g0 = dg[ms][ns][2 * half],     g1 = dg[ms][ns][2 * half + 1];
                    float u0 = du[ms][ns][2 * half],     u1 = du[ms][ns][2 * half + 1];
                    float h0 = w * u0 * g0 / (1.f + __expf(-g0));
                    float h1 = w * u1 * g1 / (1.f + __expf(-g1));
#pragma unroll
                    for (int q = 0; q < 2; q++) {
                        const int nn = n + q;
                        const int kk = nn & 15;
                        const int off = (nn >> 4) * 16 +
                                        (((kk & 3) | ((kk & 8) >> 1)) << 1) + ((kk & 4) >> 2);
                        C[off] = f2tf32f(q ? h1 : h0);
                    }
                }
            }
        }
    }
}

// ============================================================================
// Down GEMM + scatter-accumulate. 128 thr (4 warps, 2m x 2n), block 128x128,
// warp 64x64. Same 4-stage pipeline; A from packed g_Gp (no cvt ever).
// ============================================================================
__global__ void __launch_bounds__(128, 2) gemm_down_tf32(
    const float* __restrict__ dWp, const float* __restrict__ sdWp,
    float* __restrict__ out)
{
    const int e = blockIdx.z;
    const int n_e = (e < NEXP) ? g_count[e] : T_TOK;
    const int m0 = blockIdx.y * 128;
    if (m0 >= n_e) return;
    const int base = g_rowbase[e];
    const float* __restrict__ B = (e < NEXP) ? (dWp + (size_t)e * IDIM * HDIM) : sdWp;
    const int n0 = blockIdx.x * 128;

    const int tid  = threadIdx.x;
    const int warp = tid >> 5, lane = tid & 31;
    const int gi = lane >> 2, tig = lane & 3;
    const int wm = (warp & 1) * 64, wn = (warp >> 1) * 64;

    extern __shared__ float2 sm2[];
    float2* As = sm2;                    // NST * A_SF2
    float2* Bs = sm2 + NST * A_SF2;      // NST * B_SF2
    const uint32_t uAs = (uint32_t)__cvta_generic_to_shared(As);
    const uint32_t uBs = (uint32_t)__cvta_generic_to_shared(Bs);

    // A producer: idx = c*128+tid, c 0..3 -> row r=idx>>2, chunk ch=idx&3
    // B producer: idx = c*128+tid, c 0..3 -> p=idx>>6? (512 chunks: p=idx>>6, nn=(idx&63)*2)
    float dacc[4][8][4];
#pragma unroll
    for (int i = 0; i < 4; i++)
#pragma unroll
        for (int j = 0; j < 8; j++)
#pragma unroll
            for (int c = 0; c < 4; c++) dacc[i][j][c] = 0.f;

    auto issue = [&](int kt) {
        const int s = kt & (NST - 1);
#pragma unroll
        for (int c = 0; c < 4; c++) {
            int idx = c * 128 + tid;
            int r = idx >> 2, ch = idx & 3;
            const float* src = g_Gp + (size_t)(base + m0 + r) * IDIM + kt * 16 + ch * 4;
            cp_async16(uAs + (uint32_t)((s * A_SF2 + r * A_ST2 + ch * 2) * 8), src);
        }
#pragma unroll
        for (int c = 0; c < 4; c++) {
            int idx = c * 128 + tid;
            int p = idx >> 6, nn = (idx & 63) * 2;
            const float* src = B + ((size_t)(kt * 8 + p) * HDIM + n0 + nn) * 2;
            cp_async16(uBs + (uint32_t)((s * B_SF2 + p * B_ST2 + nn) * 8), src);
        }
        cp_commit();
    };

    const int NK = IDIM / 16;   // 128
    issue(0); issue(1); issue(2);
    for (int kt = 0; kt < NK; kt++) {
        cp_wait<2>();
        __syncthreads();
        if (kt + 3 < NK) issue(kt + 3); else cp_commit();

        const int s = kt & (NST - 1);
        const float2* Ab = As + s * A_SF2;
        const float2* Bb = Bs + s * B_SF2;
#pragma unroll
        for (int ks = 0; ks < 2; ks++) {
            const int pc = ks * 4 + tig;
            uint32_t af[4][4];
#pragma unroll
            for (int ms = 0; ms < 4; ms++) {
                const int mB = wm + ms * 16;
                float2 p0 = Ab[(mB + gi) * A_ST2 + pc];
                float2 p1 = Ab[(mB + 8 + gi) * A_ST2 + pc];
                af[ms][0] = __float_as_uint(p0.x);
                af[ms][1] = __float_as_uint(p1.x);
                af[ms][2] = __float_as_uint(p0.y);
                af[ms][3] = __float_as_uint(p1.y);
            }
            uint32_t bf[8][2];
#pragma unroll
            for (int ns = 0; ns < 8; ns++) {
                float2 b = Bb[pc * B_ST2 + wn + ns * 8 + gi];
                bf[ns][0] = __float_as_uint(b.x);
                bf[ns][1] = __float_as_uint(b.y);
            }
#pragma unroll
            for (int ms = 0; ms < 4; ms++)
#pragma unroll
                for (int ns = 0; ns < 8; ns++)
                    mma_tf32(dacc[ms][ns], af[ms], bf[ns]);
        }
    }

#pragma unroll
    for (int ms = 0; ms < 4; ms++) {
        const int r0 = m0 + wm + ms * 16 + gi;
        const int r1 = r0 + 8;
        if (r0 < n_e) {
            const int tok = g_ctok[base + r0];
            float* o = out + (size_t)tok * HDIM + n0 + wn;
#pragma unroll
            for (int ns = 0; ns < 8; ns++) {
                atomicAdd(o + ns * 8 + 2 * tig,     dacc[ms][ns][0]);
                atomicAdd(o + ns * 8 + 2 * tig + 1, dacc[ms][ns][1]);
            }
        }
        if (r1 < n_e) {
            const int tok = g_ctok[base + r1];
            float* o = out + (size_t)tok * HDIM + n0 + wn;
#pragma unroll
            for (int ns = 0; ns < 8; ns++) {
                atomicAdd(o + ns * 8 + 2 * tig,     dacc[ms][ns][2]);
                atomicAdd(o + ns * 8 + 2 * tig + 1, dacc[ms][ns][3]);
            }
        }
    }
}

// ---------------- host launcher ----------------------------------------------
extern "C" void kernel_launch(void* const* d_in, const int* in_sizes, int n_in,
                              void* d_out, int out_size)
{
    const float* x       = (const float*)d_in[0];
    const float* rw      = (const float*)d_in[1];
    const float* gate_w  = (const float*)d_in[2];
    const float* up_w    = (const float*)d_in[3];
    const float* down_w  = (const float*)d_in[4];
    const float* sgate_w = (const float*)d_in[5];
    const float* sup_w   = (const float*)d_in[6];
    const float* sdown_w = (const float*)d_in[7];
    float* out = (float*)d_out;

    // device pointers to packed scratch
    float *gWp, *uWp, *dWp, *sgWp, *suWp, *sdWp;
    cudaGetSymbolAddress((void**)&gWp,  g_gWp);
    cudaGetSymbolAddress((void**)&uWp,  g_uWp);
    cudaGetSymbolAddress((void**)&dWp,  g_dWp);
    cudaGetSymbolAddress((void**)&sgWp, g_sgWp);
    cudaGetSymbolAddress((void**)&suWp, g_suWp);
    cudaGetSymbolAddress((void**)&sdWp, g_sdWp);

    const int smem_gu = (NST * A_SF2 + 2 * NST * B_SF2) * 8;   // 116736
    const int smem_dn = (NST * A_SF2 + NST * B_SF2) * 8;       // 82944
    cudaFuncSetAttribute(gemm_gu_fused,
                         cudaFuncAttributeMaxDynamicSharedMemorySize, smem_gu);
    cudaFuncSetAttribute(gemm_down_tf32,
                         cudaFuncAttributeMaxDynamicSharedMemorySize, smem_dn);

    cudaMemsetAsync(out, 0, (size_t)T_TOK * HDIM * sizeof(float));

    zero_counts_kernel<<<1, 32>>>();
    router_kernel<<<ROUTER_BLOCKS, 256>>>(x, rw, out);
    finalize_kernel<<<1, 288>>>(out);
    compact_kernel<<<((NEXP + 1) * T_TOK) / 256, 256>>>();

    // pack passes (tf32 + k-pair layout)
    pack_x_kernel<<<(T_TOK * 64) / 256, 256>>>(x);
    pack_w_kernel<<<(512  * 8 * 512) / 256, 256>>>(gate_w,  gWp,  IDIM, IDIM / 4);
    pack_w_kernel<<<(512  * 8 * 512) / 256, 256>>>(up_w,    uWp,  IDIM, IDIM / 4);
    pack_w_kernel<<<(64   * 8 * 512) / 256, 256>>>(sgate_w, sgWp, IDIM, IDIM / 4);
    pack_w_kernel<<<(64   * 8 * 512) / 256, 256>>>(sup_w,   suWp, IDIM, IDIM / 4);
    pack_w_kernel<<<(1024 * 8 * 256) / 256, 256>>>(down_w,  dWp,  HDIM, HDIM / 4);
    pack_w_kernel<<<(128  * 8 * 256) / 256, 256>>>(sdown_w, sdWp, HDIM, HDIM / 4);

    dim3 grid_gu(IDIM / 128, T_TOK / 128, NEXP + 1);
    gemm_gu_fused<<<grid_gu, 256, smem_gu>>>(gWp, uWp, sgWp, suWp);

    dim3 grid_dn(HDIM / 128, T_TOK / 128, NEXP + 1);
    gemm_down_tf32<<<grid_dn, 128, smem_dn>>>(dWp, sdWp, out);
}

// round 6
// speedup vs baseline: 1.3827x; 1.3827x over previous
#include <cuda_runtime.h>
#include <cstdint>
#include <cstddef>

// Problem constants
#define T_TOK   4096
#define HDIM    1024
#define IDIM    2048
#define NEXP    8
#define TOPK    2
#define NROWS_ROUTED (T_TOK * TOPK)         // 8192
#define NROWS_TOTAL  (NROWS_ROUTED + T_TOK) // 12288
#define ROUTER_BLOCKS (T_TOK / 8)           // 512

#define OUT_AUX    (T_TOK * HDIM)
#define OUT_Z      (OUT_AUX + 1)
#define OUT_LOGITS (OUT_AUX + 2)

// ---------------- scratch ----------------------------------------------------
__device__ int   g_count[NEXP];
__device__ int   g_list[NEXP * T_TOK];
__device__ float g_wgt [NEXP * T_TOK];
__device__ int   g_rowbase[NEXP + 1];
__device__ int   g_ctok[NROWS_TOTAL];
__device__ float g_cwgt[NROWS_TOTAL];
__device__ float g_pp[ROUTER_BLOCKS * NEXP];
__device__ float g_pl[ROUTER_BLOCKS];
__device__ float g_G[(size_t)NROWS_TOTAL * IDIM];   // h (tf32-rounded)

// ---------------- helpers -----------------------------------------------------
__device__ __forceinline__ uint32_t f2tf32(float f) {
    uint32_t r;
    asm("cvt.rna.tf32.f32 %0, %1;" : "=r"(r) : "f"(f));
    return r;
}
__device__ __forceinline__ float f2tf32f(float f) {
    return __uint_as_float(f2tf32(f));
}
__device__ __forceinline__ void cp_async16(uint32_t s, const void* g) {
    asm volatile("cp.async.cg.shared.global [%0], [%1], 16;\n" :: "r"(s), "l"(g));
}
__device__ __forceinline__ void cp_commit() {
    asm volatile("cp.async.commit_group;\n");
}
template <int N>
__device__ __forceinline__ void cp_wait() {
    asm volatile("cp.async.wait_group %0;\n" :: "n"(N));
}
__device__ __forceinline__ void mma_tf32(float* d, const uint32_t* a, const uint32_t* b) {
    asm volatile(
        "mma.sync.aligned.m16n8k8.row.col.f32.tf32.tf32.f32 "
        "{%0,%1,%2,%3},{%4,%5,%6,%7},{%8,%9},{%0,%1,%2,%3};"
        : "+f"(d[0]), "+f"(d[1]), "+f"(d[2]), "+f"(d[3])
        : "r"(a[0]), "r"(a[1]), "r"(a[2]), "r"(a[3]), "r"(b[0]), "r"(b[1]));
}

// ---------------- kernel: zero counters --------------------------------------
__global__ void zero_counts_kernel() {
    if (threadIdx.x < NEXP) g_count[threadIdx.x] = 0;
}

// ---------------- router ------------------------------------------------------
__global__ void __launch_bounds__(256) router_kernel(
    const float* __restrict__ x, const float* __restrict__ rw,
    float* __restrict__ out)
{
    const int warp = threadIdx.x >> 5, lane = threadIdx.x & 31;
    const int t = blockIdx.x * 8 + warp;

    float acc[NEXP];
#pragma unroll
    for (int e = 0; e < NEXP; e++) acc[e] = 0.f;

    const float* xr = x + (size_t)t * HDIM;
    for (int h = lane; h < HDIM; h += 32) {
        float xv = xr[h];
        const float* r = rw + (size_t)h * NEXP;
#pragma unroll
        for (int e = 0; e < NEXP; e++) acc[e] += xv * r[e];
    }
#pragma unroll
    for (int off = 16; off > 0; off >>= 1)
#pragma unroll
        for (int e = 0; e < NEXP; e++)
            acc[e] += __shfl_xor_sync(0xFFFFFFFFu, acc[e], off);

    __shared__ float s_prob[8][NEXP];
    __shared__ float s_lse2[8];

    if (lane == 0) {
        float mx = acc[0];
#pragma unroll
        for (int e = 1; e < NEXP; e++) mx = fmaxf(mx, acc[e]);
        float p[NEXP], sum = 0.f;
#pragma unroll
        for (int e = 0; e < NEXP; e++) { p[e] = expf(acc[e] - mx); sum += p[e]; }
        float lse = logf(sum) + mx;
        s_lse2[warp] = lse * lse;
        float inv = 1.f / sum;
#pragma unroll
        for (int e = 0; e < NEXP; e++) {
            p[e] *= inv;
            s_prob[warp][e] = p[e];
            out[OUT_LOGITS + (size_t)t * NEXP + e] = acc[e];
        }
        int i1 = 0;
#pragma unroll
        for (int e = 1; e < NEXP; e++) if (p[e] > p[i1]) i1 = e;
        int i2 = (i1 == 0) ? 1 : 0;
#pragma unroll
        for (int e = 0; e < NEXP; e++) if (e != i2 && e != i1 && p[e] > p[i2]) i2 = e;
        float s2 = p[i1] + p[i2];
        float w1 = p[i1] / s2, w2 = p[i2] / s2;
        int pos1 = atomicAdd(&g_count[i1], 1);
        g_list[i1 * T_TOK + pos1] = t; g_wgt[i1 * T_TOK + pos1] = w1;
        int pos2 = atomicAdd(&g_count[i2], 1);
        g_list[i2 * T_TOK + pos2] = t; g_wgt[i2 * T_TOK + pos2] = w2;
    }
    __syncthreads();
    if (threadIdx.x == 0) {
        float ps[NEXP]; float l2 = 0.f;
#pragma unroll
        for (int e = 0; e < NEXP; e++) ps[e] = 0.f;
        for (int w = 0; w < 8; w++) {
            l2 += s_lse2[w];
#pragma unroll
            for (int e = 0; e < NEXP; e++) ps[e] += s_prob[w][e];
        }
#pragma unroll
        for (int e = 0; e < NEXP; e++) g_pp[blockIdx.x * NEXP + e] = ps[e];
        g_pl[blockIdx.x] = l2;
    }
}

// ---------------- finalize ----------------------------------------------------
__global__ void finalize_kernel(float* __restrict__ out) {
    const int warp = threadIdx.x >> 5, lane = threadIdx.x & 31;
    __shared__ float red[NEXP + 1];
    if (warp < NEXP) {
        float s = 0.f;
        for (int j = 0; j < ROUTER_BLOCKS / 32; j++)
            s += g_pp[(size_t)(lane + 32 * j) * NEXP + warp];
#pragma unroll
        for (int off = 16; off > 0; off >>= 1) s += __shfl_xor_sync(0xFFFFFFFFu, s, off);
        if (lane == 0) red[warp] = s;
    } else if (warp == NEXP) {
        float s = 0.f;
        for (int j = 0; j < ROUTER_BLOCKS / 32; j++)
            s += g_pl[lane + 32 * j];
#pragma unroll
        for (int off = 16; off > 0; off >>= 1) s += __shfl_xor_sync(0xFFFFFFFFu, s, off);
        if (lane == 0) red[NEXP] = s;
    }
    __syncthreads();
    if (threadIdx.x == 0) {
        float aux = 0.f;
        int rb = 0;
        for (int e = 0; e < NEXP; e++) {
            aux += ((float)g_count[e] / (float)(T_TOK * TOPK)) * (red[e] / (float)T_TOK);
            g_rowbase[e] = rb;
            rb += g_count[e];
        }
        g_rowbase[NEXP] = NROWS_ROUTED;
        out[OUT_AUX] = (float)NEXP * aux;
        out[OUT_Z]   = red[NEXP] / (float)T_TOK;
    }
}

// ---------------- compact -----------------------------------------------------
__global__ void compact_kernel() {
    int idx = blockIdx.x * blockDim.x + threadIdx.x;
    int e = idx / T_TOK, pos = idx % T_TOK;
    if (e < NEXP) {
        if (pos < g_count[e]) {
            int cr = g_rowbase[e] + pos;
            g_ctok[cr] = g_list[e * T_TOK + pos];
            g_cwgt[cr] = g_wgt[e * T_TOK + pos];
        }
    } else {
        g_ctok[NROWS_ROUTED + pos] = pos;
        g_cwgt[NROWS_ROUTED + pos] = 1.f;
    }
}

// ============================================================================
// Fused gate+up+act GEMM. 512 thr (16 warps, 4m x 4n), block tile 128 x 128
// over BOTH weight matrices, warp tile 32x32 each -> 64 acc regs/thread,
// 4 warps per SMSP for latency hiding.
// A: tid<256 stage it: LDG -> cvt.rna tf32 -> pair-pack {k,k+4} -> STS;
//    fragments via LDS.64, no in-loop CVT. Row stride 12 float2.
// B: tid>=256 issue cp.async (double buffered); fragments scalar LDS +
//    in-loop cvt (pad 136: conflict-free).
// Epilogue: h = w*silu(g)*u, rounded to tf32, written to g_G.
// ============================================================================
#define A_ST2 12     // float2 stride per A row
#define LDN   136

__global__ void __launch_bounds__(512, 1) gemm_gu_fused(
    const float* __restrict__ X,
    const float* __restrict__ Wg, const float* __restrict__ Wu,
    const float* __restrict__ Wsg, const float* __restrict__ Wsu)
{
    const int e = blockIdx.z;
    const int n_e = (e < NEXP) ? g_count[e] : T_TOK;
    const int m0 = blockIdx.y * 128;
    if (m0 >= n_e) return;
    const int base = g_rowbase[e];
    const float* __restrict__ Bg = (e < NEXP) ? (Wg + (size_t)e * HDIM * IDIM) : Wsg;
    const float* __restrict__ Bu = (e < NEXP) ? (Wu + (size_t)e * HDIM * IDIM) : Wsu;
    const int n0 = blockIdx.x * 128;

    const int tid  = threadIdx.x;
    const int warp = tid >> 5, lane = tid & 31;
    const int gi = lane >> 2, tig = lane & 3;
    const int wm = (warp & 3) * 32, wn = (warp >> 2) * 32;

    extern __shared__ float smem[];
    float2* As  = (float2*)smem;                    // 2 * 128*A_ST2 float2
    float*  Bgs = smem + 2 * 128 * A_ST2 * 2;       // 2 * 16*LDN floats
    float*  Bus = Bgs + 2 * 16 * LDN;

    uint32_t bgb = (uint32_t)__cvta_generic_to_shared(Bgs);
    uint32_t bub = (uint32_t)__cvta_generic_to_shared(Bus);

    // Role split: tid<256 stage A; tid>=256 produce B.
    const bool isA = (tid < 256);
    const int ar = (tid & 255) >> 1, akb = (tid & 1) * 8;
    const float* arow;
    {
        int tok = (m0 + ar < n_e) ? g_ctok[base + m0 + ar] : g_ctok[base];
        arow = X + (size_t)tok * HDIM + akb;
    }
    const int t2 = tid & 255;

    float dg[2][4][4], du[2][4][4];
#pragma unroll
    for (int i = 0; i < 2; i++)
#pragma unroll
        for (int j = 0; j < 4; j++)
#pragma unroll
            for (int c = 0; c < 4; c++) { dg[i][j][c] = 0.f; du[i][j][c] = 0.f; }

    auto issueB = [&](int kt, int buf) {
        const int k0 = kt * 16;
        if (!isA) {
#pragma unroll
            for (int c = 0; c < 2; c++) {
                int idx = c * 256 + t2;
                int bk = idx >> 5, bn = (idx & 31) * 4;
                uint32_t off = (uint32_t)(buf * 16 * LDN + bk * LDN + bn) * 4;
                cp_async16(bgb + off, Bg + (size_t)(k0 + bk) * IDIM + n0 + bn);
                cp_async16(bub + off, Bu + (size_t)(k0 + bk) * IDIM + n0 + bn);
            }
        }
        cp_commit();
    };
    auto stsA = [&](int buf, float4 v0, float4 v1) {
        if (isA) {
            float2* dst = As + (size_t)buf * 128 * A_ST2 + ar * A_ST2 + (akb >> 1);
            dst[0] = make_float2(f2tf32f(v0.x), f2tf32f(v1.x));
            dst[1] = make_float2(f2tf32f(v0.y), f2tf32f(v1.y));
            dst[2] = make_float2(f2tf32f(v0.z), f2tf32f(v1.z));
            dst[3] = make_float2(f2tf32f(v0.w), f2tf32f(v1.w));
        }
    };

    const int NK = HDIM / 16;   // 64
    // preamble: tile 0
    issueB(0, 0);
    float4 a0, a1;
    if (isA) {
        a0 = *(const float4*)(arow + 0);
        a1 = *(const float4*)(arow + 4);
    }
    stsA(0, a0, a1);
    cp_wait<0>();
    __syncthreads();
    if (isA) {
        a0 = *(const float4*)(arow + 16);
        a1 = *(const float4*)(arow + 20);
    }

    for (int kt = 0; kt < NK; kt++) {
        const int b = kt & 1;
        if (kt + 1 < NK) {
            issueB(kt + 1, b ^ 1);
            stsA(b ^ 1, a0, a1);
            if (isA && kt + 2 < NK) {
                a0 = *(const float4*)(arow + (kt + 2) * 16);
                a1 = *(const float4*)(arow + (kt + 2) * 16 + 4);
            }
        }
        // compute tile kt
        const float2* Ab  = As + (size_t)b * 128 * A_ST2;
        const float*  Bgb2 = Bgs + b * 16 * LDN;
        const float*  Bub2 = Bus + b * 16 * LDN;
#pragma unroll
        for (int ks = 0; ks < 2; ks++) {
            const int pc = ks * 4 + tig;   // pair column
            const int kr = ks * 8 + tig;   // B row
            uint32_t af[2][4];
#pragma unroll
            for (int ms = 0; ms < 2; ms++) {
                const int mB = wm + ms * 16;
                float2 p0 = Ab[(mB + gi) * A_ST2 + pc];
                float2 p1 = Ab[(mB + 8 + gi) * A_ST2 + pc];
                af[ms][0] = __float_as_uint(p0.x);
                af[ms][1] = __float_as_uint(p1.x);
                af[ms][2] = __float_as_uint(p0.y);
                af[ms][3] = __float_as_uint(p1.y);
            }
            uint32_t bf[4][2];
#pragma unroll
            for (int ns = 0; ns < 4; ns++) {
                const int nB = wn + ns * 8 + gi;
                bf[ns][0] = f2tf32(Bgb2[kr * LDN + nB]);
                bf[ns][1] = f2tf32(Bgb2[(kr + 4) * LDN + nB]);
            }
#pragma unroll
            for (int ms = 0; ms < 2; ms++)
#pragma unroll
                for (int ns = 0; ns < 4; ns++)
                    mma_tf32(dg[ms][ns], af[ms], bf[ns]);
#pragma unroll
            for (int ns = 0; ns < 4; ns++) {
                const int nB = wn + ns * 8 + gi;
                bf[ns][0] = f2tf32(Bub2[kr * LDN + nB]);
                bf[ns][1] = f2tf32(Bub2[(kr + 4) * LDN + nB]);
            }
#pragma unroll
            for (int ms = 0; ms < 2; ms++)
#pragma unroll
                for (int ns = 0; ns < 4; ns++)
                    mma_tf32(du[ms][ns], af[ms], bf[ns]);
        }
        if (kt + 1 < NK) cp_wait<0>();
        __syncthreads();
    }

    // epilogue: h = w * silu(g) * u, tf32-rounded, to g_G
#pragma unroll
    for (int ms = 0; ms < 2; ms++) {
#pragma unroll
        for (int half = 0; half < 2; half++) {
            const int r = m0 + wm + ms * 16 + half * 8 + gi;
            if (r < n_e) {
                const int row = base + r;
                const float w = g_cwgt[row];
                float* C = g_G + (size_t)row * IDIM + n0 + wn;
#pragma unroll
                for (int ns = 0; ns < 4; ns++) {
                    float g0 = dg[ms][ns][2 * half],     g1 = dg[ms][ns][2 * half + 1];
                    float u0 = du[ms][ns][2 * half],     u1 = du[ms][ns][2 * half + 1];
                    float h0 = w * u0 * g0 / (1.f + __expf(-g0));
                    float h1 = w * u1 * g1 / (1.f + __expf(-g1));
                    *(float2*)(C + ns * 8 + 2 * tig) =
                        make_float2(f2tf32f(h0), f2tf32f(h1));
                }
            }
        }
    }
}

// ============================================================================
// Down GEMM + scatter-accumulate. 256 thr (8 warps, 4m x 2n), warp 32x64,
// 2 CTAs/SM -> 16 warps/SM. A = g_G (tf32-clean, no cvt), K=IDIM.
// ============================================================================
#define LDK 20
__global__ void __launch_bounds__(256, 2) gemm_down_tf32(
    const float* __restrict__ W, const float* __restrict__ Wsh,
    float* __restrict__ out)
{
    const int e = blockIdx.z;
    const int n_e = (e < NEXP) ? g_count[e] : T_TOK;
    const int m0 = blockIdx.y * 128;
    if (m0 >= n_e) return;
    const int base = g_rowbase[e];
    const float* __restrict__ B = (e < NEXP) ? (W + (size_t)e * IDIM * HDIM) : Wsh;
    const int n0 = blockIdx.x * 128;

    const int tid  = threadIdx.x;
    const int warp = tid >> 5, lane = tid & 31;
    const int gi = lane >> 2, tig = lane & 3;
    const int wm = (warp & 3) * 32, wn = (warp >> 2) * 64;

    __shared__ float As[2][128 * LDK];
    __shared__ float Bs[2][16 * LDN];

    uint32_t asb[2], bsb[2];
    asb[0] = (uint32_t)__cvta_generic_to_shared(&As[0][0]);
    asb[1] = (uint32_t)__cvta_generic_to_shared(&As[1][0]);
    bsb[0] = (uint32_t)__cvta_generic_to_shared(&Bs[0][0]);
    bsb[1] = (uint32_t)__cvta_generic_to_shared(&Bs[1][0]);

    float d[2][8][4];
#pragma unroll
    for (int i = 0; i < 2; i++)
#pragma unroll
        for (int j = 0; j < 8; j++)
#pragma unroll
            for (int c = 0; c < 4; c++) d[i][j][c] = 0.f;

    auto issue_tile = [&](int kt, int buf) {
        const int k0 = kt * 16;
#pragma unroll
        for (int c = 0; c < 2; c++) {
            int idx = c * 256 + tid;
            int r = idx >> 2, ch = idx & 3;
            cp_async16(asb[buf] + (uint32_t)(r * LDK + ch * 4) * 4,
                       g_G + (size_t)(base + m0 + r) * IDIM + k0 + ch * 4);
        }
#pragma unroll
        for (int c = 0; c < 2; c++) {
            int idx = c * 256 + tid;
            int bk = idx >> 5, bn = (idx & 31) * 4;
            cp_async16(bsb[buf] + (uint32_t)(bk * LDN + bn) * 4,
                       B + (size_t)(k0 + bk) * HDIM + n0 + bn);
        }
        cp_commit();
    };

    const int NK = IDIM / 16;   // 128
    issue_tile(0, 0);
    for (int kt = 0; kt < NK; kt++) {
        const int buf = kt & 1;
        if (kt + 1 < NK) { issue_tile(kt + 1, buf ^ 1); cp_wait<1>(); }
        else             { cp_wait<0>(); }
        __syncthreads();
#pragma unroll
        for (int ks = 0; ks < 2; ks++) {
            const int kb = ks * 8;
            uint32_t af[2][4], bf[8][2];
#pragma unroll
            for (int ms = 0; ms < 2; ms++) {
                const int mB = wm + ms * 16;
                af[ms][0] = __float_as_uint(As[buf][(mB + gi)     * LDK + kb + tig]);
                af[ms][1] = __float_as_uint(As[buf][(mB + 8 + gi) * LDK + kb + tig]);
                af[ms][2] = __float_as_uint(As[buf][(mB + gi)     * LDK + kb + tig + 4]);
                af[ms][3] = __float_as_uint(As[buf][(mB + 8 + gi) * LDK + kb + tig + 4]);
            }
#pragma unroll
            for (int ns = 0; ns < 8; ns++) {
                const int nB = wn + ns * 8 + gi;
                bf[ns][0] = f2tf32(Bs[buf][(kb + tig)     * LDN + nB]);
                bf[ns][1] = f2tf32(Bs[buf][(kb + tig + 4) * LDN + nB]);
            }
#pragma unroll
            for (int ms = 0; ms < 2; ms++)
#pragma unroll
                for (int ns = 0; ns < 8; ns++)
                    mma_tf32(d[ms][ns], af[ms], bf[ns]);
        }
        __syncthreads();
    }

#pragma unroll
    for (int ms = 0; ms < 2; ms++) {
        const int r0 = m0 + wm + ms * 16 + gi;
        const int r1 = r0 + 8;
        if (r0 < n_e) {
            const int tok = g_ctok[base + r0];
            float* o = out + (size_t)tok * HDIM + n0 + wn;
#pragma unroll
            for (int ns = 0; ns < 8; ns++) {
                atomicAdd(o + ns * 8 + 2 * tig,     d[ms][ns][0]);
                atomicAdd(o + ns * 8 + 2 * tig + 1, d[ms][ns][1]);
            }
        }
        if (r1 < n_e) {
            const int tok = g_ctok[base + r1];
            float* o = out + (size_t)tok * HDIM + n0 + wn;
#pragma unroll
            for (int ns = 0; ns < 8; ns++) {
                atomicAdd(o + ns * 8 + 2 * tig,     d[ms][ns][2]);
                atomicAdd(o + ns * 8 + 2 * tig + 1, d[ms][ns][3]);
            }
        }
    }
}

// ---------------- host launcher ----------------------------------------------
extern "C" void kernel_launch(void* const* d_in, const int* in_sizes, int n_in,
                              void* d_out, int out_size)
{
    const float* x       = (const float*)d_in[0];
    const float* rw      = (const float*)d_in[1];
    const float* gate_w  = (const float*)d_in[2];
    const float* up_w    = (const float*)d_in[3];
    const float* down_w  = (const float*)d_in[4];
    const float* sgate_w = (const float*)d_in[5];
    const float* sup_w   = (const float*)d_in[6];
    const float* sdown_w = (const float*)d_in[7];
    float* out = (float*)d_out;

    // fused gu smem: A 2*128*12 float2 + B 2*2*16*LDN floats  (59392 B)
    const int smem_gu = (2 * 128 * A_ST2 * 2 + 2 * 2 * 16 * LDN) * 4;
    cudaFuncSetAttribute(gemm_gu_fused,
                         cudaFuncAttributeMaxDynamicSharedMemorySize, smem_gu);

    cudaMemsetAsync(out, 0, (size_t)T_TOK * HDIM * sizeof(float));

    zero_counts_kernel<<<1, 32>>>();
    router_kernel<<<ROUTER_BLOCKS, 256>>>(x, rw, out);
    finalize_kernel<<<1, 288>>>(out);
    compact_kernel<<<((NEXP + 1) * T_TOK) / 256, 256>>>();

    dim3 grid_gu(IDIM / 128, T_TOK / 128, NEXP + 1);
    gemm_gu_fused<<<grid_gu, 512, smem_gu>>>(x, gate_w, up_w, sgate_w, sup_w);

    dim3 grid_dn(HDIM / 128, T_TOK / 128, NEXP + 1);
    gemm_down_tf32<<<grid_dn, 256>>>(down_w, sdown_w, out);
}

// round 8
// speedup vs baseline: 2.4036x; 1.7383x over previous
#include <cuda_runtime.h>
#include <cuda_fp16.h>
#include <cstdint>
#include <cstddef>

// Problem constants
#define T_TOK   4096
#define HDIM    1024
#define IDIM    2048
#define NEXP    8
#define TOPK    2
#define NROWS_ROUTED (T_TOK * TOPK)         // 8192
#define NROWS_TOTAL  (NROWS_ROUTED + T_TOK) // 12288
#define ROUTER_BLOCKS (T_TOK / 8)           // 512

#define OUT_AUX    (T_TOK * HDIM)
#define OUT_Z      (OUT_AUX + 1)
#define OUT_LOGITS (OUT_AUX + 2)

// ---------------- scratch ----------------------------------------------------
__device__ int   g_count[NEXP];
__device__ int   g_list[NEXP * T_TOK];
__device__ float g_wgt [NEXP * T_TOK];
__device__ int   g_rowbase[NEXP + 1];
__device__ int   g_ctok[NROWS_TOTAL];
__device__ float g_cwgt[NROWS_TOTAL];
__device__ float g_pp[ROUTER_BLOCKS * NEXP];
__device__ float g_pl[ROUTER_BLOCKS];

// fp16 operands (16B-aligned for cp.async)
__device__ __align__(16) __half g_Xh [(size_t)T_TOK * HDIM];        // X fp16
__device__ __align__(16) __half g_Gh [(size_t)NROWS_TOTAL * IDIM];  // h fp16
__device__ __align__(16) __half g_gWt[(size_t)NEXP * IDIM * HDIM];  // gateW^T [e][N][K]
__device__ __align__(16) __half g_uWt[(size_t)NEXP * IDIM * HDIM];
__device__ __align__(16) __half g_dWt[(size_t)NEXP * HDIM * IDIM];  // downW^T [e][N][K]
__device__ __align__(16) __half g_sgWt[(size_t)IDIM * HDIM];
__device__ __align__(16) __half g_suWt[(size_t)IDIM * HDIM];
__device__ __align__(16) __half g_sdWt[(size_t)HDIM * IDIM];

// ---------------- helpers -----------------------------------------------------
__device__ __forceinline__ void cp_async16(uint32_t s, const void* g) {
    asm volatile("cp.async.cg.shared.global [%0], [%1], 16;\n" :: "r"(s), "l"(g));
}
__device__ __forceinline__ void cp_commit() {
    asm volatile("cp.async.commit_group;\n");
}
template <int N>
__device__ __forceinline__ void cp_wait() {
    asm volatile("cp.async.wait_group %0;\n" :: "n"(N));
}
// m16n8k16 fp16 MMA, fp32 accumulate
__device__ __forceinline__ void mma_f16(float* d, const uint32_t* a, const uint32_t* b) {
    asm volatile(
        "mma.sync.aligned.m16n8k16.row.col.f32.f16.f16.f32 "
        "{%0,%1,%2,%3},{%4,%5,%6,%7},{%8,%9},{%0,%1,%2,%3};"
        : "+f"(d[0]), "+f"(d[1]), "+f"(d[2]), "+f"(d[3])
        : "r"(a[0]), "r"(a[1]), "r"(a[2]), "r"(a[3]), "r"(b[0]), "r"(b[1]));
}

// ---------------- kernel: zero counters --------------------------------------
__global__ void zero_counts_kernel() {
    if (threadIdx.x < NEXP) g_count[threadIdx.x] = 0;
}

// ---------------- router ------------------------------------------------------
__global__ void __launch_bounds__(256) router_kernel(
    const float* __restrict__ x, const float* __restrict__ rw,
    float* __restrict__ out)
{
    const int warp = threadIdx.x >> 5, lane = threadIdx.x & 31;
    const int t = blockIdx.x * 8 + warp;

    float acc[NEXP];
#pragma unroll
    for (int e = 0; e < NEXP; e++) acc[e] = 0.f;

    const float* xr = x + (size_t)t * HDIM;
    for (int h = lane; h < HDIM; h += 32) {
        float xv = xr[h];
        const float* r = rw + (size_t)h * NEXP;
#pragma unroll
        for (int e = 0; e < NEXP; e++) acc[e] += xv * r[e];
    }
#pragma unroll
    for (int off = 16; off > 0; off >>= 1)
#pragma unroll
        for (int e = 0; e < NEXP; e++)
            acc[e] += __shfl_xor_sync(0xFFFFFFFFu, acc[e], off);

    __shared__ float s_prob[8][NEXP];
    __shared__ float s_lse2[8];

    if (lane == 0) {
        float mx = acc[0];
#pragma unroll
        for (int e = 1; e < NEXP; e++) mx = fmaxf(mx, acc[e]);
        float p[NEXP], sum = 0.f;
#pragma unroll
        for (int e = 0; e < NEXP; e++) { p[e] = expf(acc[e] - mx); sum += p[e]; }
        float lse = logf(sum) + mx;
        s_lse2[warp] = lse * lse;
        float inv = 1.f / sum;
#pragma unroll
        for (int e = 0; e < NEXP; e++) {
            p[e] *= inv;
            s_prob[warp][e] = p[e];
            out[OUT_LOGITS + (size_t)t * NEXP + e] = acc[e];
        }
        int i1 = 0;
#pragma unroll
        for (int e = 1; e < NEXP; e++) if (p[e] > p[i1]) i1 = e;
        int i2 = (i1 == 0) ? 1 : 0;
#pragma unroll
        for (int e = 0; e < NEXP; e++) if (e != i2 && e != i1 && p[e] > p[i2]) i2 = e;
        float s2 = p[i1] + p[i2];
        float w1 = p[i1] / s2, w2 = p[i2] / s2;
        int pos1 = atomicAdd(&g_count[i1], 1);
        g_list[i1 * T_TOK + pos1] = t; g_wgt[i1 * T_TOK + pos1] = w1;
        int pos2 = atomicAdd(&g_count[i2], 1);
        g_list[i2 * T_TOK + pos2] = t; g_wgt[i2 * T_TOK + pos2] = w2;
    }
    __syncthreads();
    if (threadIdx.x == 0) {
        float ps[NEXP]; float l2 = 0.f;
#pragma unroll
        for (int e = 0; e < NEXP; e++) ps[e] = 0.f;
        for (int w = 0; w < 8; w++) {
            l2 += s_lse2[w];
#pragma unroll
            for (int e = 0; e < NEXP; e++) ps[e] += s_prob[w][e];
        }
#pragma unroll
        for (int e = 0; e < NEXP; e++) g_pp[blockIdx.x * NEXP + e] = ps[e];
        g_pl[blockIdx.x] = l2;
    }
}

// ---------------- finalize ----------------------------------------------------
__global__ void finalize_kernel(float* __restrict__ out) {
    const int warp = threadIdx.x >> 5, lane = threadIdx.x & 31;
    __shared__ float red[NEXP + 1];
    if (warp < NEXP) {
        float s = 0.f;
        for (int j = 0; j < ROUTER_BLOCKS / 32; j++)
            s += g_pp[(size_t)(lane + 32 * j) * NEXP + warp];
#pragma unroll
        for (int off = 16; off > 0; off >>= 1) s += __shfl_xor_sync(0xFFFFFFFFu, s, off);
        if (lane == 0) red[warp] = s;
    } else if (warp == NEXP) {
        float s = 0.f;
        for (int j = 0; j < ROUTER_BLOCKS / 32; j++)
            s += g_pl[lane + 32 * j];
#pragma unroll
        for (int off = 16; off > 0; off >>= 1) s += __shfl_xor_sync(0xFFFFFFFFu, s, off);
        if (lane == 0) red[NEXP] = s;
    }
    __syncthreads();
    if (threadIdx.x == 0) {
        float aux = 0.f;
        int rb = 0;
        for (int e = 0; e < NEXP; e++) {
            aux += ((float)g_count[e] / (float)(T_TOK * TOPK)) * (red[e] / (float)T_TOK);
            g_rowbase[e] = rb;
            rb += g_count[e];
        }
        g_rowbase[NEXP] = NROWS_ROUTED;
        out[OUT_AUX] = (float)NEXP * aux;
        out[OUT_Z]   = red[NEXP] / (float)T_TOK;
    }
}

// ---------------- compact -----------------------------------------------------
__global__ void compact_kernel() {
    int idx = blockIdx.x * blockDim.x + threadIdx.x;
    int e = idx / T_TOK, pos = idx % T_TOK;
    if (e < NEXP) {
        if (pos < g_count[e]) {
            int cr = g_rowbase[e] + pos;
            g_ctok[cr] = g_list[e * T_TOK + pos];
            g_cwgt[cr] = g_wgt[e * T_TOK + pos];
        }
    } else {
        g_ctok[NROWS_ROUTED + pos] = pos;
        g_cwgt[NROWS_ROUTED + pos] = 1.f;
    }
}

// ---------------- pack X: fp16, same layout -----------------------------------
__global__ void pack_x_kernel(const float* __restrict__ x) {
    size_t i = ((size_t)blockIdx.x * blockDim.x + threadIdx.x) * 8;
    float4 v0 = *(const float4*)(x + i);
    float4 v1 = *(const float4*)(x + i + 4);
    __half2 h[4];
    h[0] = __floats2half2_rn(v0.x, v0.y);
    h[1] = __floats2half2_rn(v0.z, v0.w);
    h[2] = __floats2half2_rn(v1.x, v1.y);
    h[3] = __floats2half2_rn(v1.z, v1.w);
    *(uint4*)(g_Xh + i) = *(uint4*)h;
}

// ---------------- transpose+cvt: src [K][N] f32 -> dst [N][K] fp16 ------------
__global__ void transpose_cvt_kernel(const float* __restrict__ src,
                                     __half* __restrict__ dst, int K, int N) {
    __shared__ float t[32][33];
    const size_t soff = (size_t)blockIdx.z * K * N;
    int n0 = blockIdx.x * 32, k0 = blockIdx.y * 32;
    int tx = threadIdx.x, ty = threadIdx.y;   // 32 x 8
#pragma unroll
    for (int i = 0; i < 32; i += 8)
        t[ty + i][tx] = src[soff + (size_t)(k0 + ty + i) * N + n0 + tx];
    __syncthreads();
#pragma unroll
    for (int i = 0; i < 32; i += 8)
        dst[soff + (size_t)(n0 + ty + i) * K + k0 + tx] = __float2half_rn(t[tx][ty + i]);
}

// ============================================================================
// fp16 fused gate+up+act GEMM. 512 thr (16 warps, 4m x 4n), block 128x128
// over BOTH weight matrices, warp 32x32 each. K-tile 32 (2 x k16 MMA steps),
// double-buffered cp.async. SMEM rows padded to 40 halves (20 words):
// gi-row banks {0,20,8,28,16,4,24,12}+tig cover all 32 -> conflict-free LDS.32.
// Epilogue: h = w*silu(g)*u -> g_Gh (fp16).
// ============================================================================
#define PADH 40                      // halves per SMEM row
#define TILE_H (128 * PADH)          // 5120 halves = 10240 B per tile
#define GU_SMEMB (2 * 3 * TILE_H * 2)   // 61440 B
#define DN_SMEMB (2 * 2 * TILE_H * 2)   // 40960 B

__global__ void __launch_bounds__(512, 1) gemm_gu_f16(void)
{
    const int e = blockIdx.z;
    const int n_e = (e < NEXP) ? g_count[e] : T_TOK;
    const int m0 = blockIdx.y * 128;
    if (m0 >= n_e) return;
    const int base = g_rowbase[e];
    const __half* __restrict__ Bg = (e < NEXP) ? (g_gWt + (size_t)e * IDIM * HDIM) : g_sgWt;
    const __half* __restrict__ Bu = (e < NEXP) ? (g_uWt + (size_t)e * IDIM * HDIM) : g_suWt;
    const int n0 = blockIdx.x * 128;

    const int tid  = threadIdx.x;
    const int warp = tid >> 5, lane = tid & 31;
    const int gi = lane >> 2, tig = lane & 3;
    const int wm = (warp & 3) * 32, wn = (warp >> 2) * 32;

    extern __shared__ __half sh[];
    __half* As  = sh;                       // 2 stages x TILE_H
    __half* Bgs = sh + 2 * TILE_H;
    __half* Bus = sh + 4 * TILE_H;
    const uint32_t uA = (uint32_t)__cvta_generic_to_shared(As);
    const uint32_t uG = (uint32_t)__cvta_generic_to_shared(Bgs);
    const uint32_t uU = (uint32_t)__cvta_generic_to_shared(Bus);

    // producer geometry: 512 chunks (128 rows x 4) per tile, 1 chunk/thread
    const int pr = tid >> 2, pch = tid & 3;
    const __half* arow;
    {
        int tok = (m0 + pr < n_e) ? g_ctok[base + m0 + pr] : g_ctok[base];
        arow = g_Xh + (size_t)tok * HDIM + pch * 8;
    }
    const __half* bgrow = Bg + (size_t)(n0 + pr) * HDIM + pch * 8;
    const __half* burow = Bu + (size_t)(n0 + pr) * HDIM + pch * 8;
    const uint32_t dsts = (uint32_t)(pr * PADH + pch * 8) * 2;

    float dg[2][4][4], du[2][4][4];
#pragma unroll
    for (int i = 0; i < 2; i++)
#pragma unroll
        for (int j = 0; j < 4; j++)
#pragma unroll
            for (int c = 0; c < 4; c++) { dg[i][j][c] = 0.f; du[i][j][c] = 0.f; }

    auto issue = [&](int kt, int buf) {
        const int ko = kt * 32;
        const uint32_t so = (uint32_t)(buf * TILE_H * 2) + dsts;
        cp_async16(uA + so, arow + ko);
        cp_async16(uG + so, bgrow + ko);
        cp_async16(uU + so, burow + ko);
        cp_commit();
    };

    const int NK = HDIM / 32;   // 32
    issue(0, 0);
    for (int kt = 0; kt < NK; kt++) {
        const int buf = kt & 1;
        if (kt + 1 < NK) { issue(kt + 1, buf ^ 1); cp_wait<1>(); }
        else             { cp_wait<0>(); }
        __syncthreads();
        const __half* Ab = As  + buf * TILE_H;
        const __half* Gb = Bgs + buf * TILE_H;
        const __half* Ub = Bus + buf * TILE_H;
#pragma unroll
        for (int ks = 0; ks < 2; ks++) {
            const int kc = ks * 16 + 2 * tig;
            uint32_t af[2][4];
#pragma unroll
            for (int ms = 0; ms < 2; ms++) {
                const int mB = wm + ms * 16;
                af[ms][0] = *(const uint32_t*)&Ab[(mB + gi)     * PADH + kc];
                af[ms][1] = *(const uint32_t*)&Ab[(mB + 8 + gi) * PADH + kc];
                af[ms][2] = *(const uint32_t*)&Ab[(mB + gi)     * PADH + kc + 8];
                af[ms][3] = *(const uint32_t*)&Ab[(mB + 8 + gi) * PADH + kc + 8];
            }
            uint32_t bf[4][2];
#pragma unroll
            for (int ns = 0; ns < 4; ns++) {
                const int nB = wn + ns * 8 + gi;
                bf[ns][0] = *(const uint32_t*)&Gb[nB * PADH + kc];
                bf[ns][1] = *(const uint32_t*)&Gb[nB * PADH + kc + 8];
            }
#pragma unroll
            for (int ms = 0; ms < 2; ms++)
#pragma unroll
                for (int ns = 0; ns < 4; ns++)
                    mma_f16(dg[ms][ns], af[ms], bf[ns]);
#pragma unroll
            for (int ns = 0; ns < 4; ns++) {
                const int nB = wn + ns * 8 + gi;
                bf[ns][0] = *(const uint32_t*)&Ub[nB * PADH + kc];
                bf[ns][1] = *(const uint32_t*)&Ub[nB * PADH + kc + 8];
            }
#pragma unroll
            for (int ms = 0; ms < 2; ms++)
#pragma unroll
                for (int ns = 0; ns < 4; ns++)
                    mma_f16(du[ms][ns], af[ms], bf[ns]);
        }
        __syncthreads();
    }

    // epilogue: h = w * silu(g) * u -> g_Gh (fp16)
#pragma unroll
    for (int ms = 0; ms < 2; ms++) {
#pragma unroll
        for (int hh = 0; hh < 2; hh++) {
            const int r = m0 + wm + ms * 16 + hh * 8 + gi;
            if (r < n_e) {
                const int row = base + r;
                const float w = g_cwgt[row];
                __half* C = g_Gh + (size_t)row * IDIM + n0 + wn;
#pragma unroll
                for (int ns = 0; ns < 4; ns++) {
                    float g0 = dg[ms][ns][2 * hh],     g1 = dg[ms][ns][2 * hh + 1];
                    float u0 = du[ms][ns][2 * hh],     u1 = du[ms][ns][2 * hh + 1];
                    float h0 = w * u0 * g0 / (1.f + __expf(-g0));
                    float h1 = w * u1 * g1 / (1.f + __expf(-g1));
                    *(__half2*)(C + ns * 8 + 2 * tig) = __floats2half2_rn(h0, h1);
                }
            }
        }
    }
}

// ============================================================================
// fp16 down GEMM + scatter. 256 thr (8 warps, 4m x 2n), warp 32x64,
// 2 CTAs/SM. A = g_Gh compact rows (no gather), K=IDIM. fp32 atomic scatter.
// ============================================================================
__global__ void __launch_bounds__(256, 2) gemm_down_f16(float* __restrict__ out)
{
    const int e = blockIdx.z;
    const int n_e = (e < NEXP) ? g_count[e] : T_TOK;
    const int m0 = blockIdx.y * 128;
    if (m0 >= n_e) return;
    const int base = g_rowbase[e];
    const __half* __restrict__ B = (e < NEXP) ? (g_dWt + (size_t)e * HDIM * IDIM) : g_sdWt;
    const int n0 = blockIdx.x * 128;

    const int tid  = threadIdx.x;
    const int warp = tid >> 5, lane = tid & 31;
    const int gi = lane >> 2, tig = lane & 3;
    const int wm = (warp & 3) * 32, wn = (warp >> 2) * 64;

    extern __shared__ __half sh[];
    __half* As = sh;                  // 2 stages x TILE_H
    __half* Bs = sh + 2 * TILE_H;
    const uint32_t uA = (uint32_t)__cvta_generic_to_shared(As);
    const uint32_t uB = (uint32_t)__cvta_generic_to_shared(Bs);

    float d[2][8][4];
#pragma unroll
    for (int i = 0; i < 2; i++)
#pragma unroll
        for (int j = 0; j < 8; j++)
#pragma unroll
            for (int c = 0; c < 4; c++) d[i][j][c] = 0.f;

    auto issue = [&](int kt, int buf) {
        const int ko = kt * 32;
        const uint32_t bo = (uint32_t)(buf * TILE_H * 2);
#pragma unroll
        for (int c = 0; c < 2; c++) {
            int idx = c * 256 + tid;
            int r = idx >> 2, ch = idx & 3;
            uint32_t so = bo + (uint32_t)(r * PADH + ch * 8) * 2;
            cp_async16(uA + so, g_Gh + (size_t)(base + m0 + r) * IDIM + ko + ch * 8);
            cp_async16(uB + so, B + (size_t)(n0 + r) * IDIM + ko + ch * 8);
        }
        cp_commit();
    };

    const int NK = IDIM / 32;   // 64
    issue(0, 0);
    for (int kt = 0; kt < NK; kt++) {
        const int buf = kt & 1;
        if (kt + 1 < NK) { issue(kt + 1, buf ^ 1); cp_wait<1>(); }
        else             { cp_wait<0>(); }
        __syncthreads();
        const __half* Ab = As + buf * TILE_H;
        const __half* Bb = Bs + buf * TILE_H;
#pragma unroll
        for (int ks = 0; ks < 2; ks++) {
            const int kc = ks * 16 + 2 * tig;
            uint32_t af[2][4];
#pragma unroll
            for (int ms = 0; ms < 2; ms++) {
                const int mB = wm + ms * 16;
                af[ms][0] = *(const uint32_t*)&Ab[(mB + gi)     * PADH + kc];
                af[ms][1] = *(const uint32_t*)&Ab[(mB + 8 + gi) * PADH + kc];
                af[ms][2] = *(const uint32_t*)&Ab[(mB + gi)     * PADH + kc + 8];
                af[ms][3] = *(const uint32_t*)&Ab[(mB + 8 + gi) * PADH + kc + 8];
            }
            uint32_t bf[8][2];
#pragma unroll
            for (int ns = 0; ns < 8; ns++) {
                const int nB = wn + ns * 8 + gi;
                bf[ns][0] = *(const uint32_t*)&Bb[nB * PADH + kc];
                bf[ns][1] = *(const uint32_t*)&Bb[nB * PADH + kc + 8];
            }
#pragma unroll
            for (int ms = 0; ms < 2; ms++)
#pragma unroll
                for (int ns = 0; ns < 8; ns++)
                    mma_f16(d[ms][ns], af[ms], bf[ns]);
        }
        __syncthreads();
    }

#pragma unroll
    for (int ms = 0; ms < 2; ms++) {
        const int r0 = m0 + wm + ms * 16 + gi;
        const int r1 = r0 + 8;
        if (r0 < n_e) {
            const int tok = g_ctok[base + r0];
            float* o = out + (size_t)tok * HDIM + n0 + wn;
#pragma unroll
            for (int ns = 0; ns < 8; ns++) {
                atomicAdd(o + ns * 8 + 2 * tig,     d[ms][ns][0]);
                atomicAdd(o + ns * 8 + 2 * tig + 1, d[ms][ns][1]);
            }
        }
        if (r1 < n_e) {
            const int tok = g_ctok[base + r1];
            float* o = out + (size_t)tok * HDIM + n0 + wn;
#pragma unroll
            for (int ns = 0; ns < 8; ns++) {
                atomicAdd(o + ns * 8 + 2 * tig,     d[ms][ns][2]);
                atomicAdd(o + ns * 8 + 2 * tig + 1, d[ms][ns][3]);
            }
        }
    }
}

// ---------------- host launcher ----------------------------------------------
extern "C" void kernel_launch(void* const* d_in, const int* in_sizes, int n_in,
                              void* d_out, int out_size)
{
    const float* x       = (const float*)d_in[0];
    const float* rw      = (const float*)d_in[1];
    const float* gate_w  = (const float*)d_in[2];
    const float* up_w    = (const float*)d_in[3];
    const float* down_w  = (const float*)d_in[4];
    const float* sgate_w = (const float*)d_in[5];
    const float* sup_w   = (const float*)d_in[6];
    const float* sdown_w = (const float*)d_in[7];
    float* out = (float*)d_out;

    __half *gWt, *uWt, *dWt, *sgWt, *suWt, *sdWt;
    cudaGetSymbolAddress((void**)&gWt,  g_gWt);
    cudaGetSymbolAddress((void**)&uWt,  g_uWt);
    cudaGetSymbolAddress((void**)&dWt,  g_dWt);
    cudaGetSymbolAddress((void**)&sgWt, g_sgWt);
    cudaGetSymbolAddress((void**)&suWt, g_suWt);
    cudaGetSymbolAddress((void**)&sdWt, g_sdWt);

    cudaFuncSetAttribute(gemm_gu_f16,
                         cudaFuncAttributeMaxDynamicSharedMemorySize, GU_SMEMB);
    cudaFuncSetAttribute(gemm_down_f16,
                         cudaFuncAttributeMaxDynamicSharedMemorySize, DN_SMEMB);

    cudaMemsetAsync(out, 0, (size_t)T_TOK * HDIM * sizeof(float));

    zero_counts_kernel<<<1, 32>>>();
    router_kernel<<<ROUTER_BLOCKS, 256>>>(x, rw, out);
    finalize_kernel<<<1, 288>>>(out);
    compact_kernel<<<((NEXP + 1) * T_TOK) / 256, 256>>>();

    pack_x_kernel<<<(T_TOK * HDIM / 8) / 256, 256>>>(x);
    dim3 tb(32, 8);
    transpose_cvt_kernel<<<dim3(IDIM / 32, HDIM / 32, NEXP), tb>>>(gate_w,  gWt,  HDIM, IDIM);
    transpose_cvt_kernel<<<dim3(IDIM / 32, HDIM / 32, NEXP), tb>>>(up_w,    uWt,  HDIM, IDIM);
    transpose_cvt_kernel<<<dim3(IDIM / 32, HDIM / 32, 1),    tb>>>(sgate_w, sgWt, HDIM, IDIM);
    transpose_cvt_kernel<<<dim3(IDIM / 32, HDIM / 32, 1),    tb>>>(sup_w,   suWt, HDIM, IDIM);
    transpose_cvt_kernel<<<dim3(HDIM / 32, IDIM / 32, NEXP), tb>>>(down_w,  dWt,  IDIM, HDIM);
    transpose_cvt_kernel<<<dim3(HDIM / 32, IDIM / 32, 1),    tb>>>(sdown_w, sdWt, IDIM, HDIM);

    dim3 grid_gu(IDIM / 128, T_TOK / 128, NEXP + 1);
    gemm_gu_f16<<<grid_gu, 512, GU_SMEMB>>>();

    dim3 grid_dn(HDIM / 128, T_TOK / 128, NEXP + 1);
    gemm_down_f16<<<grid_dn, 256, DN_SMEMB>>>(out);
}

// round 9
// speedup vs baseline: 2.7398x; 1.1399x over previous
#include <cuda_runtime.h>
#include <cuda_fp16.h>
#include <cstdint>
#include <cstddef>

// Problem constants
#define T_TOK   4096
#define HDIM    1024
#define IDIM    2048
#define NEXP    8
#define TOPK    2
#define NROWS_ROUTED (T_TOK * TOPK)         // 8192
#define NROWS_TOTAL  (NROWS_ROUTED + T_TOK) // 12288
#define ROUTER_BLOCKS (T_TOK / 8)           // 512

#define OUT_AUX    (T_TOK * HDIM)
#define OUT_Z      (OUT_AUX + 1)
#define OUT_LOGITS (OUT_AUX + 2)

// ---------------- scratch ----------------------------------------------------
__device__ int   g_count[NEXP];
__device__ int   g_list[NEXP * T_TOK];
__device__ float g_wgt [NEXP * T_TOK];
__device__ int   g_rowbase[NEXP + 1];
__device__ int   g_ctok[NROWS_TOTAL];
__device__ float g_cwgt[NROWS_TOTAL];
__device__ float g_pp[ROUTER_BLOCKS * NEXP];
__device__ float g_pl[ROUTER_BLOCKS];

// fp16 operands (16B-aligned for cp.async)
__device__ __align__(16) __half g_Xh [(size_t)T_TOK * HDIM];
__device__ __align__(16) __half g_Gh [(size_t)NROWS_TOTAL * IDIM];
__device__ __align__(16) __half g_gWt[(size_t)NEXP * IDIM * HDIM];  // [e][N][K]
__device__ __align__(16) __half g_uWt[(size_t)NEXP * IDIM * HDIM];
__device__ __align__(16) __half g_dWt[(size_t)NEXP * HDIM * IDIM];
__device__ __align__(16) __half g_sgWt[(size_t)IDIM * HDIM];
__device__ __align__(16) __half g_suWt[(size_t)IDIM * HDIM];
__device__ __align__(16) __half g_sdWt[(size_t)HDIM * IDIM];

// ---------------- helpers -----------------------------------------------------
__device__ __forceinline__ void cp_async16(uint32_t s, const void* g) {
    asm volatile("cp.async.cg.shared.global [%0], [%1], 16;\n" :: "r"(s), "l"(g));
}
__device__ __forceinline__ void cp_commit() {
    asm volatile("cp.async.commit_group;\n");
}
template <int N>
__device__ __forceinline__ void cp_wait() {
    asm volatile("cp.async.wait_group %0;\n" :: "n"(N));
}
__device__ __forceinline__ void mma_f16(float* d, const uint32_t* a, const uint32_t* b) {
    asm volatile(
        "mma.sync.aligned.m16n8k16.row.col.f32.f16.f16.f32 "
        "{%0,%1,%2,%3},{%4,%5,%6,%7},{%8,%9},{%0,%1,%2,%3};"
        : "+f"(d[0]), "+f"(d[1]), "+f"(d[2]), "+f"(d[3])
        : "r"(a[0]), "r"(a[1]), "r"(a[2]), "r"(a[3]), "r"(b[0]), "r"(b[1]));
}

// ---------------- kernel: zero counters --------------------------------------
__global__ void zero_counts_kernel() {
    if (threadIdx.x < NEXP) g_count[threadIdx.x] = 0;
}

// ---------------- router ------------------------------------------------------
__global__ void __launch_bounds__(256) router_kernel(
    const float* __restrict__ x, const float* __restrict__ rw,
    float* __restrict__ out)
{
    const int warp = threadIdx.x >> 5, lane = threadIdx.x & 31;
    const int t = blockIdx.x * 8 + warp;

    float acc[NEXP];
#pragma unroll
    for (int e = 0; e < NEXP; e++) acc[e] = 0.f;

    const float* xr = x + (size_t)t * HDIM;
    for (int h = lane; h < HDIM; h += 32) {
        float xv = xr[h];
        const float* r = rw + (size_t)h * NEXP;
#pragma unroll
        for (int e = 0; e < NEXP; e++) acc[e] += xv * r[e];
    }
#pragma unroll
    for (int off = 16; off > 0; off >>= 1)
#pragma unroll
        for (int e = 0; e < NEXP; e++)
            acc[e] += __shfl_xor_sync(0xFFFFFFFFu, acc[e], off);

    __shared__ float s_prob[8][NEXP];
    __shared__ float s_lse2[8];

    if (lane == 0) {
        float mx = acc[0];
#pragma unroll
        for (int e = 1; e < NEXP; e++) mx = fmaxf(mx, acc[e]);
        float p[NEXP], sum = 0.f;
#pragma unroll
        for (int e = 0; e < NEXP; e++) { p[e] = expf(acc[e] - mx); sum += p[e]; }
        float lse = logf(sum) + mx;
        s_lse2[warp] = lse * lse;
        float inv = 1.f / sum;
#pragma unroll
        for (int e = 0; e < NEXP; e++) {
            p[e] *= inv;
            s_prob[warp][e] = p[e];
            out[OUT_LOGITS + (size_t)t * NEXP + e] = acc[e];
        }
        int i1 = 0;
#pragma unroll
        for (int e = 1; e < NEXP; e++) if (p[e] > p[i1]) i1 = e;
        int i2 = (i1 == 0) ? 1 : 0;
#pragma unroll
        for (int e = 0; e < NEXP; e++) if (e != i2 && e != i1 && p[e] > p[i2]) i2 = e;
        float s2 = p[i1] + p[i2];
        float w1 = p[i1] / s2, w2 = p[i2] / s2;
        int pos1 = atomicAdd(&g_count[i1], 1);
        g_list[i1 * T_TOK + pos1] = t; g_wgt[i1 * T_TOK + pos1] = w1;
        int pos2 = atomicAdd(&g_count[i2], 1);
        g_list[i2 * T_TOK + pos2] = t; g_wgt[i2 * T_TOK + pos2] = w2;
    }
    __syncthreads();
    if (threadIdx.x == 0) {
        float ps[NEXP]; float l2 = 0.f;
#pragma unroll
        for (int e = 0; e < NEXP; e++) ps[e] = 0.f;
        for (int w = 0; w < 8; w++) {
            l2 += s_lse2[w];
#pragma unroll
            for (int e = 0; e < NEXP; e++) ps[e] += s_prob[w][e];
        }
#pragma unroll
        for (int e = 0; e < NEXP; e++) g_pp[blockIdx.x * NEXP + e] = ps[e];
        g_pl[blockIdx.x] = l2;
    }
}

// ---------------- finalize ----------------------------------------------------
__global__ void finalize_kernel(float* __restrict__ out) {
    const int warp = threadIdx.x >> 5, lane = threadIdx.x & 31;
    __shared__ float red[NEXP + 1];
    if (warp < NEXP) {
        float s = 0.f;
        for (int j = 0; j < ROUTER_BLOCKS / 32; j++)
            s += g_pp[(size_t)(lane + 32 * j) * NEXP + warp];
#pragma unroll
        for (int off = 16; off > 0; off >>= 1) s += __shfl_xor_sync(0xFFFFFFFFu, s, off);
        if (lane == 0) red[warp] = s;
    } else if (warp == NEXP) {
        float s = 0.f;
        for (int j = 0; j < ROUTER_BLOCKS / 32; j++)
            s += g_pl[lane + 32 * j];
#pragma unroll
        for (int off = 16; off > 0; off >>= 1) s += __shfl_xor_sync(0xFFFFFFFFu, s, off);
        if (lane == 0) red[NEXP] = s;
    }
    __syncthreads();
    if (threadIdx.x == 0) {
        float aux = 0.f;
        int rb = 0;
        for (int e = 0; e < NEXP; e++) {
            aux += ((float)g_count[e] / (float)(T_TOK * TOPK)) * (red[e] / (float)T_TOK);
            g_rowbase[e] = rb;
            rb += g_count[e];
        }
        g_rowbase[NEXP] = NROWS_ROUTED;
        out[OUT_AUX] = (float)NEXP * aux;
        out[OUT_Z]   = red[NEXP] / (float)T_TOK;
    }
}

// ---------------- compact -----------------------------------------------------
__global__ void compact_kernel() {
    int idx = blockIdx.x * blockDim.x + threadIdx.x;
    int e = idx / T_TOK, pos = idx % T_TOK;
    if (e < NEXP) {
        if (pos < g_count[e]) {
            int cr = g_rowbase[e] + pos;
            g_ctok[cr] = g_list[e * T_TOK + pos];
            g_cwgt[cr] = g_wgt[e * T_TOK + pos];
        }
    } else {
        g_ctok[NROWS_ROUTED + pos] = pos;
        g_cwgt[NROWS_ROUTED + pos] = 1.f;
    }
}

// ---------------- pack X ------------------------------------------------------
__global__ void pack_x_kernel(const float* __restrict__ x) {
    size_t i = ((size_t)blockIdx.x * blockDim.x + threadIdx.x) * 8;
    float4 v0 = *(const float4*)(x + i);
    float4 v1 = *(const float4*)(x + i + 4);
    __half2 h[4];
    h[0] = __floats2half2_rn(v0.x, v0.y);
    h[1] = __floats2half2_rn(v0.z, v0.w);
    h[2] = __floats2half2_rn(v1.x, v1.y);
    h[3] = __floats2half2_rn(v1.z, v1.w);
    *(uint4*)(g_Xh + i) = *(uint4*)h;
}

// ---------------- batched transpose+cvt: [K][N] f32 -> [N][K] fp16 ------------
__device__ __forceinline__ void transpose_tile(
    const float* __restrict__ src, __half* __restrict__ dst, int K, int N,
    int n0, int k0, int tx, int ty)
{
    __shared__ float t[32][33];
#pragma unroll
    for (int i = 0; i < 32; i += 8)
        t[ty + i][tx] = src[(size_t)(k0 + ty + i) * N + n0 + tx];
    __syncthreads();
#pragma unroll
    for (int i = 0; i < 32; i += 8)
        dst[(size_t)(n0 + ty + i) * K + k0 + tx] = __float2half_rn(t[tx][ty + i]);
}

// gu weights: K=HDIM, N=IDIM; z: 0..7 gate, 8..15 up, 16 sgate, 17 sup
__global__ void cvt_gu_w_kernel(const float* __restrict__ gate_w,
                                const float* __restrict__ up_w,
                                const float* __restrict__ sg_w,
                                const float* __restrict__ su_w)
{
    const int z = blockIdx.z;
    const float* src; __half* dst;
    if (z < 8)       { src = gate_w + (size_t)z * HDIM * IDIM;        dst = g_gWt + (size_t)z * IDIM * HDIM; }
    else if (z < 16) { src = up_w   + (size_t)(z - 8) * HDIM * IDIM;  dst = g_uWt + (size_t)(z - 8) * IDIM * HDIM; }
    else if (z == 16){ src = sg_w;  dst = g_sgWt; }
    else             { src = su_w;  dst = g_suWt; }
    transpose_tile(src, dst, HDIM, IDIM, blockIdx.x * 32, blockIdx.y * 32,
                   threadIdx.x, threadIdx.y);
}
// down weights: K=IDIM, N=HDIM; z: 0..7 down, 8 sdown
__global__ void cvt_dn_w_kernel(const float* __restrict__ down_w,
                                const float* __restrict__ sd_w)
{
    const int z = blockIdx.z;
    const float* src; __half* dst;
    if (z < 8) { src = down_w + (size_t)z * IDIM * HDIM; dst = g_dWt + (size_t)z * HDIM * IDIM; }
    else       { src = sd_w;  dst = g_sdWt; }
    transpose_tile(src, dst, IDIM, HDIM, blockIdx.x * 32, blockIdx.y * 32,
                   threadIdx.x, threadIdx.y);
}

// ============================================================================
// fp16 fused gate+up+act GEMM. 512 thr (16 warps, 4m x 4n), block 128x128,
// warp 32x32 each. K-tile 64 (4 x k16 MMA steps), double-buffered cp.async.
// SMEM rows padded to 72 halves (36 words, 144B = 16B-mult): fragment LDS.32
// banks = (4*gi + tig) mod 32 -> all 32 lanes distinct. Epilogue -> g_Gh.
// ============================================================================
#define PADH 72                      // halves per SMEM row
#define TILE_H (128 * PADH)          // 9216 halves = 18432 B per tile
#define GU_SMEMB (2 * 3 * TILE_H * 2)   // 110592 B
#define DN_SMEMB (2 * 2 * TILE_H * 2)   // 73728 B

__global__ void __launch_bounds__(512, 1) gemm_gu_f16(void)
{
    const int e = blockIdx.z;
    const int n_e = (e < NEXP) ? g_count[e] : T_TOK;
    const int m0 = blockIdx.y * 128;
    if (m0 >= n_e) return;
    const int base = g_rowbase[e];
    const __half* __restrict__ Bg = (e < NEXP) ? (g_gWt + (size_t)e * IDIM * HDIM) : g_sgWt;
    const __half* __restrict__ Bu = (e < NEXP) ? (g_uWt + (size_t)e * IDIM * HDIM) : g_suWt;
    const int n0 = blockIdx.x * 128;

    const int tid  = threadIdx.x;
    const int warp = tid >> 5, lane = tid & 31;
    const int gi = lane >> 2, tig = lane & 3;
    const int wm = (warp & 3) * 32, wn = (warp >> 2) * 32;

    extern __shared__ __half sh[];
    __half* As  = sh;
    __half* Bgs = sh + 2 * TILE_H;
    __half* Bus = sh + 4 * TILE_H;
    const uint32_t uA = (uint32_t)__cvta_generic_to_shared(As);
    const uint32_t uG = (uint32_t)__cvta_generic_to_shared(Bgs);
    const uint32_t uU = (uint32_t)__cvta_generic_to_shared(Bus);

    // producer: 1024 16B-chunks per matrix per tile; 512 thr -> 2 chunks each
    const int pr0 = tid >> 3, pch = tid & 7;        // c=0 row; c=1 row = pr0+64
    const __half* arow0;
    const __half* arow1;
    {
        int t0 = (m0 + pr0 < n_e)      ? g_ctok[base + m0 + pr0]      : g_ctok[base];
        int t1 = (m0 + pr0 + 64 < n_e) ? g_ctok[base + m0 + pr0 + 64] : g_ctok[base];
        arow0 = g_Xh + (size_t)t0 * HDIM + pch * 8;
        arow1 = g_Xh + (size_t)t1 * HDIM + pch * 8;
    }
    const __half* bgrow = Bg + (size_t)(n0 + pr0) * HDIM + pch * 8;
    const __half* burow = Bu + (size_t)(n0 + pr0) * HDIM + pch * 8;
    const size_t BROW64 = (size_t)64 * HDIM;
    const uint32_t d0 = (uint32_t)(pr0 * PADH + pch * 8) * 2;
    const uint32_t d1 = d0 + (uint32_t)(64 * PADH) * 2;

    float dg[2][4][4], du[2][4][4];
#pragma unroll
    for (int i = 0; i < 2; i++)
#pragma unroll
        for (int j = 0; j < 4; j++)
#pragma unroll
            for (int c = 0; c < 4; c++) { dg[i][j][c] = 0.f; du[i][j][c] = 0.f; }

    auto issue = [&](int kt, int buf) {
        const int ko = kt * 64;
        const uint32_t bo = (uint32_t)(buf * TILE_H * 2);
        cp_async16(uA + bo + d0, arow0 + ko);
        cp_async16(uA + bo + d1, arow1 + ko);
        cp_async16(uG + bo + d0, bgrow + ko);
        cp_async16(uG + bo + d1, bgrow + BROW64 + ko);
        cp_async16(uU + bo + d0, burow + ko);
        cp_async16(uU + bo + d1, burow + BROW64 + ko);
        cp_commit();
    };

    const int NK = HDIM / 64;   // 16
    issue(0, 0);
    for (int kt = 0; kt < NK; kt++) {
        const int buf = kt & 1;
        if (kt + 1 < NK) { issue(kt + 1, buf ^ 1); cp_wait<1>(); }
        else             { cp_wait<0>(); }
        __syncthreads();
        const __half* Ab = As  + buf * TILE_H;
        const __half* Gb = Bgs + buf * TILE_H;
        const __half* Ub = Bus + buf * TILE_H;
#pragma unroll
        for (int ks = 0; ks < 4; ks++) {
            const int kc = ks * 16 + 2 * tig;
            uint32_t af[2][4];
#pragma unroll
            for (int ms = 0; ms < 2; ms++) {
                const int mB = wm + ms * 16;
                af[ms][0] = *(const uint32_t*)&Ab[(mB + gi)     * PADH + kc];
                af[ms][1] = *(const uint32_t*)&Ab[(mB + 8 + gi) * PADH + kc];
                af[ms][2] = *(const uint32_t*)&Ab[(mB + gi)     * PADH + kc + 8];
                af[ms][3] = *(const uint32_t*)&Ab[(mB + 8 + gi) * PADH + kc + 8];
            }
            uint32_t bf[4][2];
#pragma unroll
            for (int ns = 0; ns < 4; ns++) {
                const int nB = wn + ns * 8 + gi;
                bf[ns][0] = *(const uint32_t*)&Gb[nB * PADH + kc];
                bf[ns][1] = *(const uint32_t*)&Gb[nB * PADH + kc + 8];
            }
#pragma unroll
            for (int ms = 0; ms < 2; ms++)
#pragma unroll
                for (int ns = 0; ns < 4; ns++)
                    mma_f16(dg[ms][ns], af[ms], bf[ns]);
#pragma unroll
            for (int ns = 0; ns < 4; ns++) {
                const int nB = wn + ns * 8 + gi;
                bf[ns][0] = *(const uint32_t*)&Ub[nB * PADH + kc];
                bf[ns][1] = *(const uint32_t*)&Ub[nB * PADH + kc + 8];
            }
#pragma unroll
            for (int ms = 0; ms < 2; ms++)
#pragma unroll
                for (int ns = 0; ns < 4; ns++)
                    mma_f16(du[ms][ns], af[ms], bf[ns]);
        }
        __syncthreads();
    }

    // epilogue: h = w * silu(g) * u -> g_Gh (fp16)
#pragma unroll
    for (int ms = 0; ms < 2; ms++) {
#pragma unroll
        for (int hh = 0; hh < 2; hh++) {
            const int r = m0 + wm + ms * 16 + hh * 8 + gi;
            if (r < n_e) {
                const int row = base + r;
                const float w = g_cwgt[row];
                __half* C = g_Gh + (size_t)row * IDIM + n0 + wn;
#pragma unroll
                for (int ns = 0; ns < 4; ns++) {
                    float g0 = dg[ms][ns][2 * hh],     g1 = dg[ms][ns][2 * hh + 1];
                    float u0 = du[ms][ns][2 * hh],     u1 = du[ms][ns][2 * hh + 1];
                    float h0 = w * u0 * g0 / (1.f + __expf(-g0));
                    float h1 = w * u1 * g1 / (1.f + __expf(-g1));
                    *(__half2*)(C + ns * 8 + 2 * tig) = __floats2half2_rn(h0, h1);
                }
            }
        }
    }
}

// ============================================================================
// fp16 down GEMM + scatter. 256 thr (8 warps, 4m x 2n), warp 32x64,
// 2 CTAs/SM. K-tile 64. A = g_Gh compact rows, fp32 atomic scatter.
// ============================================================================
__global__ void __launch_bounds__(256, 2) gemm_down_f16(float* __restrict__ out)
{
    const int e = blockIdx.z;
    const int n_e = (e < NEXP) ? g_count[e] : T_TOK;
    const int m0 = blockIdx.y * 128;
    if (m0 >= n_e) return;
    const int base = g_rowbase[e];
    const __half* __restrict__ B = (e < NEXP) ? (g_dWt + (size_t)e * HDIM * IDIM) : g_sdWt;
    const int n0 = blockIdx.x * 128;

    const int tid  = threadIdx.x;
    const int warp = tid >> 5, lane = tid & 31;
    const int gi = lane >> 2, tig = lane & 3;
    const int wm = (warp & 3) * 32, wn = (warp >> 2) * 64;

    extern __shared__ __half sh[];
    __half* As = sh;
    __half* Bs = sh + 2 * TILE_H;
    const uint32_t uA = (uint32_t)__cvta_generic_to_shared(As);
    const uint32_t uB = (uint32_t)__cvta_generic_to_shared(Bs);

    // producer: 1024 chunks per matrix per tile; 256 thr -> 4 chunks each
    const int pr0 = tid >> 3, pch = tid & 7;   // rows pr0 + 32*c
    const __half* arow = g_Gh + (size_t)(base + m0 + pr0) * IDIM + pch * 8;
    const __half* brow = B + (size_t)(n0 + pr0) * IDIM + pch * 8;
    const size_t ROW32 = (size_t)32 * IDIM;
    const uint32_t ds0 = (uint32_t)(pr0 * PADH + pch * 8) * 2;
    const uint32_t SROW32 = (uint32_t)(32 * PADH) * 2;

    float d[2][8][4];
#pragma unroll
    for (int i = 0; i < 2; i++)
#pragma unroll
        for (int j = 0; j < 8; j++)
#pragma unroll
            for (int c = 0; c < 4; c++) d[i][j][c] = 0.f;

    auto issue = [&](int kt, int buf) {
        const int ko = kt * 64;
        const uint32_t bo = (uint32_t)(buf * TILE_H * 2);
#pragma unroll
        for (int c = 0; c < 4; c++) {
            cp_async16(uA + bo + ds0 + c * SROW32, arow + c * ROW32 + ko);
            cp_async16(uB + bo + ds0 + c * SROW32, brow + c * ROW32 + ko);
        }
        cp_commit();
    };

    const int NK = IDIM / 64;   // 32
    issue(0, 0);
    for (int kt = 0; kt < NK; kt++) {
        const int buf = kt & 1;
        if (kt + 1 < NK) { issue(kt + 1, buf ^ 1); cp_wait<1>(); }
        else             { cp_wait<0>(); }
        __syncthreads();
        const __half* Ab = As + buf * TILE_H;
        const __half* Bb = Bs + buf * TILE_H;
#pragma unroll
        for (int ks = 0; ks < 4; ks++) {
            const int kc = ks * 16 + 2 * tig;
            uint32_t af[2][4];
#pragma unroll
            for (int ms = 0; ms < 2; ms++) {
                const int mB = wm + ms * 16;
                af[ms][0] = *(const uint32_t*)&Ab[(mB + gi)     * PADH + kc];
                af[ms][1] = *(const uint32_t*)&Ab[(mB + 8 + gi) * PADH + kc];
                af[ms][2] = *(const uint32_t*)&Ab[(mB + gi)     * PADH + kc + 8];
                af[ms][3] = *(const uint32_t*)&Ab[(mB + 8 + gi) * PADH + kc + 8];
            }
            uint32_t bf[8][2];
#pragma unroll
            for (int ns = 0; ns < 8; ns++) {
                const int nB = wn + ns * 8 + gi;
                bf[ns][0] = *(const uint32_t*)&Bb[nB * PADH + kc];
                bf[ns][1] = *(const uint32_t*)&Bb[nB * PADH + kc + 8];
            }
#pragma unroll
            for (int ms = 0; ms < 2; ms++)
#pragma unroll
                for (int ns = 0; ns < 8; ns++)
                    mma_f16(d[ms][ns], af[ms], bf[ns]);
        }
        __syncthreads();
    }

#pragma unroll
    for (int ms = 0; ms < 2; ms++) {
        const int r0 = m0 + wm + ms * 16 + gi;
        const int r1 = r0 + 8;
        if (r0 < n_e) {
            const int tok = g_ctok[base + r0];
            float* o = out + (size_t)tok * HDIM + n0 + wn;
#pragma unroll
            for (int ns = 0; ns < 8; ns++) {
                atomicAdd(o + ns * 8 + 2 * tig,     d[ms][ns][0]);
                atomicAdd(o + ns * 8 + 2 * tig + 1, d[ms][ns][1]);
            }
        }
        if (r1 < n_e) {
            const int tok = g_ctok[base + r1];
            float* o = out + (size_t)tok * HDIM + n0 + wn;
#pragma unroll
            for (int ns = 0; ns < 8; ns++) {
                atomicAdd(o + ns * 8 + 2 * tig,     d[ms][ns][2]);
                atomicAdd(o + ns * 8 + 2 * tig + 1, d[ms][ns][3]);
            }
        }
    }
}

// ---------------- host launcher ----------------------------------------------
extern "C" void kernel_launch(void* const* d_in, const int* in_sizes, int n_in,
                              void* d_out, int out_size)
{
    const float* x       = (const float*)d_in[0];
    const float* rw      = (const float*)d_in[1];
    const float* gate_w  = (const float*)d_in[2];
    const float* up_w    = (const float*)d_in[3];
    const float* down_w  = (const float*)d_in[4];
    const float* sgate_w = (const float*)d_in[5];
    const float* sup_w   = (const float*)d_in[6];
    const float* sdown_w = (const float*)d_in[7];
    float* out = (float*)d_out;

    cudaFuncSetAttribute(gemm_gu_f16,
                         cudaFuncAttributeMaxDynamicSharedMemorySize, GU_SMEMB);
    cudaFuncSetAttribute(gemm_down_f16,
                         cudaFuncAttributeMaxDynamicSharedMemorySize, DN_SMEMB);

    cudaMemsetAsync(out, 0, (size_t)T_TOK * HDIM * sizeof(float));

    zero_counts_kernel<<<1, 32>>>();
    router_kernel<<<ROUTER_BLOCKS, 256>>>(x, rw, out);
    finalize_kernel<<<1, 288>>>(out);
    compact_kernel<<<((NEXP + 1) * T_TOK) / 256, 256>>>();

    pack_x_kernel<<<(T_TOK * HDIM / 8) / 256, 256>>>(x);
    dim3 tb(32, 8);
    cvt_gu_w_kernel<<<dim3(IDIM / 32, HDIM / 32, 18), tb>>>(gate_w, up_w, sgate_w, sup_w);
    cvt_dn_w_kernel<<<dim3(HDIM / 32, IDIM / 32, 9),  tb>>>(down_w, sdown_w);

    dim3 grid_gu(IDIM / 128, T_TOK / 128, NEXP + 1);
    gemm_gu_f16<<<grid_gu, 512, GU_SMEMB>>>();

    dim3 grid_dn(HDIM / 128, T_TOK / 128, NEXP + 1);
    gemm_down_f16<<<grid_dn, 256, DN_SMEMB>>>(out);
}

// round 10
// speedup vs baseline: 2.7740x; 1.0125x over previous
#include <cuda_runtime.h>
#include <cuda_fp16.h>
#include <cstdint>
#include <cstddef>

// Problem constants
#define T_TOK   4096
#define HDIM    1024
#define IDIM    2048
#define NEXP    8
#define TOPK    2
#define NROWS_ROUTED (T_TOK * TOPK)         // 8192
#define NROWS_TOTAL  (NROWS_ROUTED + T_TOK) // 12288
#define ROUTER_BLOCKS (T_TOK / 8)           // 512

#define OUT_AUX    (T_TOK * HDIM)
#define OUT_Z      (OUT_AUX + 1)
#define OUT_LOGITS (OUT_AUX + 2)

// ---------------- scratch ----------------------------------------------------
__device__ int   g_count[NEXP];
__device__ int   g_list[NEXP * T_TOK];
__device__ float g_wgt [NEXP * T_TOK];
__device__ int   g_rowbase[NEXP + 1];
__device__ int   g_ctok[NROWS_TOTAL];
__device__ float g_cwgt[NROWS_TOTAL];
__device__ float g_pp[ROUTER_BLOCKS * NEXP];
__device__ float g_pl[ROUTER_BLOCKS];

// fp16 operands (16B-aligned for cp.async)
__device__ __align__(16) __half g_Xh [(size_t)T_TOK * HDIM];
__device__ __align__(16) __half g_Gh [(size_t)NROWS_TOTAL * IDIM];
__device__ __align__(16) __half g_gWt[(size_t)NEXP * IDIM * HDIM];  // [e][N][K]
__device__ __align__(16) __half g_uWt[(size_t)NEXP * IDIM * HDIM];
__device__ __align__(16) __half g_dWt[(size_t)NEXP * HDIM * IDIM];
__device__ __align__(16) __half g_sgWt[(size_t)IDIM * HDIM];
__device__ __align__(16) __half g_suWt[(size_t)IDIM * HDIM];
__device__ __align__(16) __half g_sdWt[(size_t)HDIM * IDIM];

// ---------------- helpers -----------------------------------------------------
__device__ __forceinline__ void cp_async16(uint32_t s, const void* g) {
    asm volatile("cp.async.cg.shared.global [%0], [%1], 16;\n" :: "r"(s), "l"(g));
}
__device__ __forceinline__ void cp_commit() {
    asm volatile("cp.async.commit_group;\n");
}
template <int N>
__device__ __forceinline__ void cp_wait() {
    asm volatile("cp.async.wait_group %0;\n" :: "n"(N));
}
__device__ __forceinline__ void mma_f16(float* d, const uint32_t* a, const uint32_t* b) {
    asm volatile(
        "mma.sync.aligned.m16n8k16.row.col.f32.f16.f16.f32 "
        "{%0,%1,%2,%3},{%4,%5,%6,%7},{%8,%9},{%0,%1,%2,%3};"
        : "+f"(d[0]), "+f"(d[1]), "+f"(d[2]), "+f"(d[3])
        : "r"(a[0]), "r"(a[1]), "r"(a[2]), "r"(a[3]), "r"(b[0]), "r"(b[1]));
}

// ---------------- kernel: zero counters --------------------------------------
__global__ void zero_counts_kernel() {
    if (threadIdx.x < NEXP) g_count[threadIdx.x] = 0;
}

// ---------------- router (+ fused X->fp16 conversion) -------------------------
__global__ void __launch_bounds__(256) router_kernel(
    const float* __restrict__ x, const float* __restrict__ rw,
    float* __restrict__ out)
{
    const int warp = threadIdx.x >> 5, lane = threadIdx.x & 31;
    const int t = blockIdx.x * 8 + warp;

    float acc[NEXP];
#pragma unroll
    for (int e = 0; e < NEXP; e++) acc[e] = 0.f;

    const float* xr = x + (size_t)t * HDIM;
    for (int h = lane; h < HDIM; h += 32) {
        float xv = xr[h];
        const float* r = rw + (size_t)h * NEXP;
#pragma unroll
        for (int e = 0; e < NEXP; e++) acc[e] += xv * r[e];
    }
    // fused fp16 conversion of this token's row (L2-hot)
    {
        __half2* dst = (__half2*)(g_Xh + (size_t)t * HDIM);
        for (int h = lane; h < HDIM / 2; h += 32) {
            float2 v = *(const float2*)(xr + 2 * h);
            dst[h] = __floats2half2_rn(v.x, v.y);
        }
    }
#pragma unroll
    for (int off = 16; off > 0; off >>= 1)
#pragma unroll
        for (int e = 0; e < NEXP; e++)
            acc[e] += __shfl_xor_sync(0xFFFFFFFFu, acc[e], off);

    __shared__ float s_prob[8][NEXP];
    __shared__ float s_lse2[8];

    if (lane == 0) {
        float mx = acc[0];
#pragma unroll
        for (int e = 1; e < NEXP; e++) mx = fmaxf(mx, acc[e]);
        float p[NEXP], sum = 0.f;
#pragma unroll
        for (int e = 0; e < NEXP; e++) { p[e] = expf(acc[e] - mx); sum += p[e]; }
        float lse = logf(sum) + mx;
        s_lse2[warp] = lse * lse;
        float inv = 1.f / sum;
#pragma unroll
        for (int e = 0; e < NEXP; e++) {
            p[e] *= inv;
            s_prob[warp][e] = p[e];
            out[OUT_LOGITS + (size_t)t * NEXP + e] = acc[e];
        }
        int i1 = 0;
#pragma unroll
        for (int e = 1; e < NEXP; e++) if (p[e] > p[i1]) i1 = e;
        int i2 = (i1 == 0) ? 1 : 0;
#pragma unroll
        for (int e = 0; e < NEXP; e++) if (e != i2 && e != i1 && p[e] > p[i2]) i2 = e;
        float s2 = p[i1] + p[i2];
        float w1 = p[i1] / s2, w2 = p[i2] / s2;
        int pos1 = atomicAdd(&g_count[i1], 1);
        g_list[i1 * T_TOK + pos1] = t; g_wgt[i1 * T_TOK + pos1] = w1;
        int pos2 = atomicAdd(&g_count[i2], 1);
        g_list[i2 * T_TOK + pos2] = t; g_wgt[i2 * T_TOK + pos2] = w2;
    }
    __syncthreads();
    if (threadIdx.x == 0) {
        float ps[NEXP]; float l2 = 0.f;
#pragma unroll
        for (int e = 0; e < NEXP; e++) ps[e] = 0.f;
        for (int w = 0; w < 8; w++) {
            l2 += s_lse2[w];
#pragma unroll
            for (int e = 0; e < NEXP; e++) ps[e] += s_prob[w][e];
        }
#pragma unroll
        for (int e = 0; e < NEXP; e++) g_pp[blockIdx.x * NEXP + e] = ps[e];
        g_pl[blockIdx.x] = l2;
    }
}

// ---------------- finalize ----------------------------------------------------
__global__ void finalize_kernel(float* __restrict__ out) {
    const int warp = threadIdx.x >> 5, lane = threadIdx.x & 31;
    __shared__ float red[NEXP + 1];
    if (warp < NEXP) {
        float s = 0.f;
        for (int j = 0; j < ROUTER_BLOCKS / 32; j++)
            s += g_pp[(size_t)(lane + 32 * j) * NEXP + warp];
#pragma unroll
        for (int off = 16; off > 0; off >>= 1) s += __shfl_xor_sync(0xFFFFFFFFu, s, off);
        if (lane == 0) red[warp] = s;
    } else if (warp == NEXP) {
        float s = 0.f;
        for (int j = 0; j < ROUTER_BLOCKS / 32; j++)
            s += g_pl[lane + 32 * j];
#pragma unroll
        for (int off = 16; off > 0; off >>= 1) s += __shfl_xor_sync(0xFFFFFFFFu, s, off);
        if (lane == 0) red[NEXP] = s;
    }
    __syncthreads();
    if (threadIdx.x == 0) {
        float aux = 0.f;
        int rb = 0;
        for (int e = 0; e < NEXP; e++) {
            aux += ((float)g_count[e] / (float)(T_TOK * TOPK)) * (red[e] / (float)T_TOK);
            g_rowbase[e] = rb;
            rb += g_count[e];
        }
        g_rowbase[NEXP] = NROWS_ROUTED;
        out[OUT_AUX] = (float)NEXP * aux;
        out[OUT_Z]   = red[NEXP] / (float)T_TOK;
    }
}

// ---------------- compact -----------------------------------------------------
__global__ void compact_kernel() {
    int idx = blockIdx.x * blockDim.x + threadIdx.x;
    int e = idx / T_TOK, pos = idx % T_TOK;
    if (e < NEXP) {
        if (pos < g_count[e]) {
            int cr = g_rowbase[e] + pos;
            g_ctok[cr] = g_list[e * T_TOK + pos];
            g_cwgt[cr] = g_wgt[e * T_TOK + pos];
        }
    } else {
        g_ctok[NROWS_ROUTED + pos] = pos;
        g_cwgt[NROWS_ROUTED + pos] = 1.f;
    }
}

// ---------------- batched transpose+cvt: [K][N] f32 -> [N][K] fp16 ------------
__device__ __forceinline__ void transpose_tile(
    const float* __restrict__ src, __half* __restrict__ dst, int K, int N,
    int n0, int k0, int tx, int ty)
{
    __shared__ float t[32][33];
#pragma unroll
    for (int i = 0; i < 32; i += 8)
        t[ty + i][tx] = src[(size_t)(k0 + ty + i) * N + n0 + tx];
    __syncthreads();
#pragma unroll
    for (int i = 0; i < 32; i += 8)
        dst[(size_t)(n0 + ty + i) * K + k0 + tx] = __float2half_rn(t[tx][ty + i]);
}

__global__ void cvt_gu_w_kernel(const float* __restrict__ gate_w,
                                const float* __restrict__ up_w,
                                const float* __restrict__ sg_w,
                                const float* __restrict__ su_w)
{
    const int z = blockIdx.z;
    const float* src; __half* dst;
    if (z < 8)       { src = gate_w + (size_t)z * HDIM * IDIM;        dst = g_gWt + (size_t)z * IDIM * HDIM; }
    else if (z < 16) { src = up_w   + (size_t)(z - 8) * HDIM * IDIM;  dst = g_uWt + (size_t)(z - 8) * IDIM * HDIM; }
    else if (z == 16){ src = sg_w;  dst = g_sgWt; }
    else             { src = su_w;  dst = g_suWt; }
    transpose_tile(src, dst, HDIM, IDIM, blockIdx.x * 32, blockIdx.y * 32,
                   threadIdx.x, threadIdx.y);
}
__global__ void cvt_dn_w_kernel(const float* __restrict__ down_w,
                                const float* __restrict__ sd_w)
{
    const int z = blockIdx.z;
    const float* src; __half* dst;
    if (z < 8) { src = down_w + (size_t)z * IDIM * HDIM; dst = g_dWt + (size_t)z * HDIM * IDIM; }
    else       { src = sd_w;  dst = g_sdWt; }
    transpose_tile(src, dst, IDIM, HDIM, blockIdx.x * 32, blockIdx.y * 32,
                   threadIdx.x, threadIdx.y);
}

// ============================================================================
// fp16 fused gate+up+act GEMM. 512 thr (16 warps, 4m x 4n), block 128x128,
// warp 32x32 each. K-tile 64, 3-STAGE cp.async pipeline, ONE barrier per kt.
// SMEM rows padded to 72 halves: fragment LDS.32 banks (4*gi+tig) all distinct.
// ============================================================================
#define PADH 72                      // halves per SMEM row
#define TILE_H (128 * PADH)          // 9216 halves = 18432 B per tile
#define NSTG 3
#define GU_SMEMB (NSTG * 3 * TILE_H * 2)   // 165888 B
#define DN_SMEMB (NSTG * 2 * TILE_H * 2)   // 110592 B

__global__ void __launch_bounds__(512, 1) gemm_gu_f16(void)
{
    const int e = blockIdx.z;
    const int n_e = (e < NEXP) ? g_count[e] : T_TOK;
    const int m0 = blockIdx.y * 128;
    if (m0 >= n_e) return;
    const int base = g_rowbase[e];
    const __half* __restrict__ Bg = (e < NEXP) ? (g_gWt + (size_t)e * IDIM * HDIM) : g_sgWt;
    const __half* __restrict__ Bu = (e < NEXP) ? (g_uWt + (size_t)e * IDIM * HDIM) : g_suWt;
    const int n0 = blockIdx.x * 128;

    const int tid  = threadIdx.x;
    const int warp = tid >> 5, lane = tid & 31;
    const int gi = lane >> 2, tig = lane & 3;
    const int wm = (warp & 3) * 32, wn = (warp >> 2) * 32;

    extern __shared__ __half sh[];
    __half* As  = sh;                       // NSTG x TILE_H
    __half* Bgs = sh + NSTG * TILE_H;
    __half* Bus = sh + 2 * NSTG * TILE_H;
    const uint32_t uA = (uint32_t)__cvta_generic_to_shared(As);
    const uint32_t uG = (uint32_t)__cvta_generic_to_shared(Bgs);
    const uint32_t uU = (uint32_t)__cvta_generic_to_shared(Bus);

    // producer: 1024 16B-chunks per matrix per tile; 512 thr -> 2 chunks each
    const int pr0 = tid >> 3, pch = tid & 7;
    const __half* arow0;
    const __half* arow1;
    {
        int t0 = (m0 + pr0 < n_e)      ? g_ctok[base + m0 + pr0]      : g_ctok[base];
        int t1 = (m0 + pr0 + 64 < n_e) ? g_ctok[base + m0 + pr0 + 64] : g_ctok[base];
        arow0 = g_Xh + (size_t)t0 * HDIM + pch * 8;
        arow1 = g_Xh + (size_t)t1 * HDIM + pch * 8;
    }
    const __half* bgrow = Bg + (size_t)(n0 + pr0) * HDIM + pch * 8;
    const __half* burow = Bu + (size_t)(n0 + pr0) * HDIM + pch * 8;
    const size_t BROW64 = (size_t)64 * HDIM;
    const uint32_t d0 = (uint32_t)(pr0 * PADH + pch * 8) * 2;
    const uint32_t d1 = d0 + (uint32_t)(64 * PADH) * 2;

    float dg[2][4][4], du[2][4][4];
#pragma unroll
    for (int i = 0; i < 2; i++)
#pragma unroll
        for (int j = 0; j < 4; j++)
#pragma unroll
            for (int c = 0; c < 4; c++) { dg[i][j][c] = 0.f; du[i][j][c] = 0.f; }

    auto issue = [&](int kt, int s) {
        const int ko = kt * 64;
        const uint32_t bo = (uint32_t)(s * TILE_H * 2);
        cp_async16(uA + bo + d0, arow0 + ko);
        cp_async16(uA + bo + d1, arow1 + ko);
        cp_async16(uG + bo + d0, bgrow + ko);
        cp_async16(uG + bo + d1, bgrow + BROW64 + ko);
        cp_async16(uU + bo + d0, burow + ko);
        cp_async16(uU + bo + d1, burow + BROW64 + ko);
        cp_commit();
    };

    const int NK = HDIM / 64;   // 16
    issue(0, 0);
    issue(1, 1);
    int sbuf = 0;                // kt % 3
    for (int kt = 0; kt < NK; kt++) {
        if (kt + 1 < NK) cp_wait<1>(); else cp_wait<0>();
        __syncthreads();
        if (kt + 2 < NK) {
            int s2 = sbuf + 2; if (s2 >= NSTG) s2 -= NSTG;
            issue(kt + 2, s2);
        }
        const __half* Ab = As  + sbuf * TILE_H;
        const __half* Gb = Bgs + sbuf * TILE_H;
        const __half* Ub = Bus + sbuf * TILE_H;
#pragma unroll
        for (int ks = 0; ks < 4; ks++) {
            const int kc = ks * 16 + 2 * tig;
            uint32_t af[2][4];
#pragma unroll
            for (int ms = 0; ms < 2; ms++) {
                const int mB = wm + ms * 16;
                af[ms][0] = *(const uint32_t*)&Ab[(mB + gi)     * PADH + kc];
                af[ms][1] = *(const uint32_t*)&Ab[(mB + 8 + gi) * PADH + kc];
                af[ms][2] = *(const uint32_t*)&Ab[(mB + gi)     * PADH + kc + 8];
                af[ms][3] = *(const uint32_t*)&Ab[(mB + 8 + gi) * PADH + kc + 8];
            }
            uint32_t bf[4][2];
#pragma unroll
            for (int ns = 0; ns < 4; ns++) {
                const int nB = wn + ns * 8 + gi;
                bf[ns][0] = *(const uint32_t*)&Gb[nB * PADH + kc];
                bf[ns][1] = *(const uint32_t*)&Gb[nB * PADH + kc + 8];
            }
#pragma unroll
            for (int ms = 0; ms < 2; ms++)
#pragma unroll
                for (int ns = 0; ns < 4; ns++)
                    mma_f16(dg[ms][ns], af[ms], bf[ns]);
#pragma unroll
            for (int ns = 0; ns < 4; ns++) {
                const int nB = wn + ns * 8 + gi;
                bf[ns][0] = *(const uint32_t*)&Ub[nB * PADH + kc];
                bf[ns][1] = *(const uint32_t*)&Ub[nB * PADH + kc + 8];
            }
#pragma unroll
            for (int ms = 0; ms < 2; ms++)
#pragma unroll
                for (int ns = 0; ns < 4; ns++)
                    mma_f16(du[ms][ns], af[ms], bf[ns]);
        }
        if (++sbuf == NSTG) sbuf = 0;
    }

    // epilogue: h = w * silu(g) * u -> g_Gh (fp16)
#pragma unroll
    for (int ms = 0; ms < 2; ms++) {
#pragma unroll
        for (int hh = 0; hh < 2; hh++) {
            const int r = m0 + wm + ms * 16 + hh * 8 + gi;
            if (r < n_e) {
                const int row = base + r;
                const float w = g_cwgt[row];
                __half* C = g_Gh + (size_t)row * IDIM + n0 + wn;
#pragma unroll
                for (int ns = 0; ns < 4; ns++) {
                    float g0 = dg[ms][ns][2 * hh],     g1 = dg[ms][ns][2 * hh + 1];
                    float u0 = du[ms][ns][2 * hh],     u1 = du[ms][ns][2 * hh + 1];
                    float h0 = w * u0 * g0 / (1.f + __expf(-g0));
                    float h1 = w * u1 * g1 / (1.f + __expf(-g1));
                    *(__half2*)(C + ns * 8 + 2 * tig) = __floats2half2_rn(h0, h1);
                }
            }
        }
    }
}

// ============================================================================
// fp16 down GEMM + scatter. 256 thr (8 warps, 4m x 2n), warp 32x64,
// 2 CTAs/SM. K-tile 64, 3-stage pipeline, one barrier per kt.
// ============================================================================
__global__ void __launch_bounds__(256, 2) gemm_down_f16(float* __restrict__ out)
{
    const int e = blockIdx.z;
    const int n_e = (e < NEXP) ? g_count[e] : T_TOK;
    const int m0 = blockIdx.y * 128;
    if (m0 >= n_e) return;
    const int base = g_rowbase[e];
    const __half* __restrict__ B = (e < NEXP) ? (g_dWt + (size_t)e * HDIM * IDIM) : g_sdWt;
    const int n0 = blockIdx.x * 128;

    const int tid  = threadIdx.x;
    const int warp = tid >> 5, lane = tid & 31;
    const int gi = lane >> 2, tig = lane & 3;
    const int wm = (warp & 3) * 32, wn = (warp >> 2) * 64;

    extern __shared__ __half sh[];
    __half* As = sh;                   // NSTG x TILE_H
    __half* Bs = sh + NSTG * TILE_H;
    const uint32_t uA = (uint32_t)__cvta_generic_to_shared(As);
    const uint32_t uB = (uint32_t)__cvta_generic_to_shared(Bs);

    const int pr0 = tid >> 3, pch = tid & 7;   // rows pr0 + 32*c
    const __half* arow = g_Gh + (size_t)(base + m0 + pr0) * IDIM + pch * 8;
    const __half* brow = B + (size_t)(n0 + pr0) * IDIM + pch * 8;
    const size_t ROW32 = (size_t)32 * IDIM;
    const uint32_t ds0 = (uint32_t)(pr0 * PADH + pch * 8) * 2;
    const uint32_t SROW32 = (uint32_t)(32 * PADH) * 2;

    float d[2][8][4];
#pragma unroll
    for (int i = 0; i < 2; i++)
#pragma unroll
        for (int j = 0; j < 8; j++)
#pragma unroll
            for (int c = 0; c < 4; c++) d[i][j][c] = 0.f;

    auto issue = [&](int kt, int s) {
        const int ko = kt * 64;
        const uint32_t bo = (uint32_t)(s * TILE_H * 2);
#pragma unroll
        for (int c = 0; c < 4; c++) {
            cp_async16(uA + bo + ds0 + c * SROW32, arow + c * ROW32 + ko);
            cp_async16(uB + bo + ds0 + c * SROW32, brow + c * ROW32 + ko);
        }
        cp_commit();
    };

    const int NK = IDIM / 64;   // 32
    issue(0, 0);
    issue(1, 1);
    int sbuf = 0;
    for (int kt = 0; kt < NK; kt++) {
        if (kt + 1 < NK) cp_wait<1>(); else cp_wait<0>();
        __syncthreads();
        if (kt + 2 < NK) {
            int s2 = sbuf + 2; if (s2 >= NSTG) s2 -= NSTG;
            issue(kt + 2, s2);
        }
        const __half* Ab = As + sbuf * TILE_H;
        const __half* Bb = Bs + sbuf * TILE_H;
#pragma unroll
        for (int ks = 0; ks < 4; ks++) {
            const int kc = ks * 16 + 2 * tig;
            uint32_t af[2][4];
#pragma unroll
            for (int ms = 0; ms < 2; ms++) {
                const int mB = wm + ms * 16;
                af[ms][0] = *(const uint32_t*)&Ab[(mB + gi)     * PADH + kc];
                af[ms][1] = *(const uint32_t*)&Ab[(mB + 8 + gi) * PADH + kc];
                af[ms][2] = *(const uint32_t*)&Ab[(mB + gi)     * PADH + kc + 8];
                af[ms][3] = *(const uint32_t*)&Ab[(mB + 8 + gi) * PADH + kc + 8];
            }
            uint32_t bf[8][2];
#pragma unroll
            for (int ns = 0; ns < 8; ns++) {
                const int nB = wn + ns * 8 + gi;
                bf[ns][0] = *(const uint32_t*)&Bb[nB * PADH + kc];
                bf[ns][1] = *(const uint32_t*)&Bb[nB * PADH + kc + 8];
            }
#pragma unroll
            for (int ms = 0; ms < 2; ms++)
#pragma unroll
                for (int ns = 0; ns < 8; ns++)
                    mma_f16(d[ms][ns], af[ms], bf[ns]);
        }
        if (++sbuf == NSTG) sbuf = 0;
    }

#pragma unroll
    for (int ms = 0; ms < 2; ms++) {
        const int r0 = m0 + wm + ms * 16 + gi;
        const int r1 = r0 + 8;
        if (r0 < n_e) {
            const int tok = g_ctok[base + r0];
            float* o = out + (size_t)tok * HDIM + n0 + wn;
#pragma unroll
            for (int ns = 0; ns < 8; ns++) {
                atomicAdd(o + ns * 8 + 2 * tig,     d[ms][ns][0]);
                atomicAdd(o + ns * 8 + 2 * tig + 1, d[ms][ns][1]);
            }
        }
        if (r1 < n_e) {
            const int tok = g_ctok[base + r1];
            float* o = out + (size_t)tok * HDIM + n0 + wn;
#pragma unroll
            for (int ns = 0; ns < 8; ns++) {
                atomicAdd(o + ns * 8 + 2 * tig,     d[ms][ns][2]);
                atomicAdd(o + ns * 8 + 2 * tig + 1, d[ms][ns][3]);
            }
        }
    }
}

// ---------------- host launcher ----------------------------------------------
extern "C" void kernel_launch(void* const* d_in, const int* in_sizes, int n_in,
                              void* d_out, int out_size)
{
    const float* x       = (const float*)d_in[0];
    const float* rw      = (const float*)d_in[1];
    const float* gate_w  = (const float*)d_in[2];
    const float* up_w    = (const float*)d_in[3];
    const float* down_w  = (const float*)d_in[4];
    const float* sgate_w = (const float*)d_in[5];
    const float* sup_w   = (const float*)d_in[6];
    const float* sdown_w = (const float*)d_in[7];
    float* out = (float*)d_out;

    cudaFuncSetAttribute(gemm_gu_f16,
                         cudaFuncAttributeMaxDynamicSharedMemorySize, GU_SMEMB);
    cudaFuncSetAttribute(gemm_down_f16,
                         cudaFuncAttributeMaxDynamicSharedMemorySize, DN_SMEMB);

    cudaMemsetAsync(out, 0, (size_t)T_TOK * HDIM * sizeof(float));

    zero_counts_kernel<<<1, 32>>>();
    router_kernel<<<ROUTER_BLOCKS, 256>>>(x, rw, out);
    finalize_kernel<<<1, 288>>>(out);
    compact_kernel<<<((NEXP + 1) * T_TOK) / 256, 256>>>();

    dim3 tb(32, 8);
    cvt_gu_w_kernel<<<dim3(IDIM / 32, HDIM / 32, 18), tb>>>(gate_w, up_w, sgate_w, sup_w);
    cvt_dn_w_kernel<<<dim3(HDIM / 32, IDIM / 32, 9),  tb>>>(down_w, sdown_w);

    dim3 grid_gu(IDIM / 128, T_TOK / 128, NEXP + 1);
    gemm_gu_f16<<<grid_gu, 512, GU_SMEMB>>>();

    dim3 grid_dn(HDIM / 128, T_TOK / 128, NEXP + 1);
    gemm_down_f16<<<grid_dn, 256, DN_SMEMB>>>(out);
}